// round 12
// baseline (speedup 1.0000x reference)
#include <cuda_runtime.h>
#include <cuda_bf16.h>
#include <cstdint>
#include <math.h>

#define TOKV 21760            // per-view feature tokens: 4*(4096+1024+256+64)
#define AROWS 43520           // 2 views
#define KVSZ  11141120        // 43520*256
#define MPAD  1664            // 1600 padded to 13*128

__constant__ int c_N[4]   = {4096, 1024, 256, 64};
__constant__ int c_off[4] = {0, 16384, 20480, 21504};
// 22 cross-attn split slots (256-key chunks; level 3 has 64)
__constant__ int c_sl[22] = {0,0,0,0,0,0,0,0,0,0,0,0,0,0,0,0, 1,1,1,1, 2, 3};
__constant__ int c_sk[22] = {0,1,2,3,4,5,6,7,8,9,10,11,12,13,14,15, 0,1,2,3, 0, 0};
__constant__ int c_ck[22] = {256,256,256,256,256,256,256,256,256,256,256,256,256,256,256,256,
                             256,256,256,256, 256, 64};
__constant__ int c_S[4]  = {16,4,1,1};
__constant__ int c_s0[4] = {0,16,20,21};

// ---- device scratch (allocations forbidden) ----
__device__ float g_kv[12*KVSZ];
__device__ __nv_bfloat16 g_ahi[AROWS*256];
__device__ __nv_bfloat16 g_alo[AROWS*256];
__device__ __nv_bfloat16 g_whi[12*256*256];
__device__ __nv_bfloat16 g_wlo[12*256*256];
__device__ float g_bkv[12*256];
__device__ __nv_bfloat16 g_qh[MPAD*256],  g_ql[MPAD*256];
__device__ __nv_bfloat16 g_oh[MPAD*256],  g_ol[MPAD*256];
__device__ __nv_bfloat16 g_och[3200*256], g_ocl[3200*256];
__device__ __nv_bfloat16 g_wqkvh[6*768*256], g_wqkvl[6*768*256];
__device__ __nv_bfloat16 g_wswh[6*256*256],  g_wswl[6*256*256];
__device__ __nv_bfloat16 g_wqh[6*256*256],   g_wql[6*256*256];
__device__ __nv_bfloat16 g_wph[6*256*256],   g_wpl[6*256*256];
__device__ float g_bsw[1536], g_bwq[1536], g_bwp[1536];
__device__ float g_buf[9000000];

struct FeatPtrs { const float* p[8]; };

// ---------------- PTX helpers ----------------
__device__ __forceinline__ uint32_t smem_u32(const void* p){
    uint32_t a;
    asm("{ .reg .u64 t; cvta.to.shared.u64 t, %1; cvt.u32.u64 %0, t; }" : "=r"(a) : "l"(p));
    return a;
}
__device__ __forceinline__ void cp16(uint32_t s, const void* g){
    asm volatile("cp.async.cg.shared.global [%0], [%1], 16;" :: "r"(s), "l"(g) : "memory");
}
__device__ __forceinline__ void cp_commit(){
    asm volatile("cp.async.commit_group;" ::: "memory");
}
template<int N>
__device__ __forceinline__ void cp_wait(){
    asm volatile("cp.async.wait_group %0;" :: "n"(N) : "memory");
}
__device__ __forceinline__ void ldsm4(uint32_t* r, uint32_t a){
    asm volatile("ldmatrix.sync.aligned.m8n8.x4.shared.b16 {%0,%1,%2,%3}, [%4];"
                 : "=r"(r[0]), "=r"(r[1]), "=r"(r[2]), "=r"(r[3]) : "r"(a));
}
__device__ __forceinline__ void mma16816(float* c, const uint32_t* a,
                                         uint32_t b0, uint32_t b1){
    asm volatile(
        "mma.sync.aligned.m16n8k16.row.col.f32.bf16.bf16.f32 "
        "{%0,%1,%2,%3}, {%4,%5,%6,%7}, {%8,%9}, {%0,%1,%2,%3};"
        : "+f"(c[0]), "+f"(c[1]), "+f"(c[2]), "+f"(c[3])
        : "r"(a[0]), "r"(a[1]), "r"(a[2]), "r"(a[3]), "r"(b0), "r"(b1));
}
__device__ __forceinline__ void hilo(float v, __nv_bfloat16* ph, __nv_bfloat16* pl){
    __nv_bfloat16 h = __float2bfloat16(v);
    *ph = h;
    *pl = __float2bfloat16(v - __bfloat162float(h));
}
__device__ __forceinline__ uint32_t pack2(float a, float b){
    __nv_bfloat16 h0 = __float2bfloat16(a);
    __nv_bfloat16 h1 = __float2bfloat16(b);
    return (uint32_t)__bfloat16_as_ushort(h0) | ((uint32_t)__bfloat16_as_ushort(h1) << 16);
}

// ---------------- reductions ----------------
__device__ __forceinline__ float warpSum(float v){
#pragma unroll
    for (int o = 16; o > 0; o >>= 1) v += __shfl_xor_sync(0xffffffffu, v, o);
    return v;
}
__device__ __forceinline__ float warpMax(float v){
#pragma unroll
    for (int o = 16; o > 0; o >>= 1) v = fmaxf(v, __shfl_xor_sync(0xffffffffu, v, o));
    return v;
}

// ---- tokenize + LN normalization -> bf16 hi/lo ----
__global__ void __launch_bounds__(256) k_tok_ln(FeatPtrs fp,
    __nv_bfloat16* __restrict__ ahi, __nv_bfloat16* __restrict__ alo)
{
    __shared__ float s[256][33];
    __shared__ float ps[8][32], pq[8][32];
    __shared__ float mean[32], rinv[32];
    int r = blockIdx.x, v = blockIdx.y;
    int l = (r < 512) ? 0 : (r < 640) ? 1 : (r < 672) ? 2 : 3;
    int off32 = (l == 0) ? 0 : (l == 1) ? 512 : (l == 2) ? 640 : 672;
    int Nl = c_N[l];
    int idx = r - off32;
    int tpb = Nl >> 5;
    int b = idx / tpb, t0 = (idx % tpb) * 32;
    const float* f = fp.p[v*4 + l];
    int g = threadIdx.x >> 5, t = threadIdx.x & 31;
    for (int cc = g; cc < 256; cc += 8)
        s[cc][t] = f[((size_t)(b*256 + cc))*Nl + t0 + t];
    __syncthreads();
    float sx = 0.f, sq = 0.f;
#pragma unroll
    for (int k = 0; k < 32; k++){
        float x = s[g*32 + k][t];
        sx += x; sq = fmaf(x, x, sq);
    }
    ps[g][t] = sx; pq[g][t] = sq;
    __syncthreads();
    if (threadIdx.x < 32){
        float m = 0.f, qq = 0.f;
#pragma unroll
        for (int gg = 0; gg < 8; gg++){ m += ps[gg][threadIdx.x]; qq += pq[gg][threadIdx.x]; }
        m *= (1.f/256.f);
        float var = qq*(1.f/256.f) - m*m;
        mean[threadIdx.x] = m;
        rinv[threadIdx.x] = rsqrtf(var + 1e-5f);
    }
    __syncthreads();
    int c = threadIdx.x;
    size_t rowbase = (size_t)v*TOKV + c_off[l] + (size_t)b*Nl + t0;
    for (int tt = 0; tt < 32; tt++){
        float val = (s[c][tt] - mean[tt]) * rinv[tt];
        hilo(val, &ahi[(rowbase + tt)*256 + c], &alo[(rowbase + tt)*256 + c]);
    }
}

// ---- prep KV weights ----
__global__ void __launch_bounds__(256) k_prep_w(
    const float* __restrict__ wk, const float* __restrict__ wv,
    const float* __restrict__ ng, const float* __restrict__ nb,
    __nv_bfloat16* __restrict__ whi, __nv_bfloat16* __restrict__ wlo,
    float* __restrict__ bkv)
{
    int s = blockIdx.x, n = threadIdx.x;
    int d = s >> 1;
    const float* W = ((s & 1) ? wv : wk) + (size_t)d*65536;
    const float* g = ng + d*256;
    const float* b = nb + d*256;
    float bias = 0.f;
    size_t obase = ((size_t)s*256 + n)*256;
    for (int k = 0; k < 256; k++){
        float w0 = W[k*256 + n];
        bias = fmaf(b[k], w0, bias);
        float w = g[k]*w0;
        hilo(w, &whi[obase + k], &wlo[obase + k]);
    }
    bkv[s*256 + n] = bias;
}

// ---- generic weight prep ----
__global__ void __launch_bounds__(256) k_prep_wt(
    const float* __restrict__ W, const float* __restrict__ g,
    const float* __restrict__ bf, const float* __restrict__ ab,
    __nv_bfloat16* __restrict__ wh, __nv_bfloat16* __restrict__ wl,
    float* __restrict__ bo, int N)
{
    int d = blockIdx.y;
    int n = blockIdx.x*256 + threadIdx.x;
    const float* Wd = W + (size_t)d*256*N;
    float bias = ab ? ab[(size_t)d*N + n] : 0.f;
    size_t ob = ((size_t)d*N + n)*256;
    for (int k = 0; k < 256; k++){
        float w0 = Wd[(size_t)k*N + n];
        if (bf) bias = fmaf(bf[d*256 + k], w0, bias);
        float w = g ? g[d*256 + k]*w0 : w0;
        hilo(w, &wh[ob + k], &wl[ob + k]);
    }
    if (bo) bo[(size_t)d*N + n] = bias;
}

__global__ void k_init_q(const float* __restrict__ qe,
                         __nv_bfloat16* __restrict__ qh,
                         __nv_bfloat16* __restrict__ ql){
    int row = blockIdx.x, c = threadIdx.x;
    float val = qe[(row % 100)*256 + c];
    hilo(val, &qh[(size_t)row*256 + c], &ql[(size_t)row*256 + c]);
}

// ---- mma.sync KV GEMM, 512 threads ----
__global__ void __launch_bounds__(512) k_kvgemm(
    const __nv_bfloat16* __restrict__ Ahi, const __nv_bfloat16* __restrict__ Alo,
    const __nv_bfloat16* __restrict__ Whi, const __nv_bfloat16* __restrict__ Wlo,
    const float* __restrict__ bkv, float* __restrict__ Cbuf)
{
    extern __shared__ char sm[];
    uint32_t sb = smem_u32(sm);
    int tid = threadIdx.x, lane = tid & 31, warp = tid >> 5;
    int mt = blockIdx.x, nh = blockIdx.y, slot = blockIdx.z;
    size_t arow0 = (size_t)mt * 128;
    const __nv_bfloat16* wh = Whi + (size_t)slot*65536 + (size_t)nh*128*256;
    const __nv_bfloat16* wl = Wlo + (size_t)slot*65536 + (size_t)nh*128*256;

    int wm = warp >> 2, wn = warp & 3;           // warp tile: 32m x 32n

    float acc[2][4][4];
#pragma unroll
    for (int mi = 0; mi < 2; mi++)
#pragma unroll
        for (int ni = 0; ni < 4; ni++)
#pragma unroll
            for (int k = 0; k < 4; k++) acc[mi][ni][k] = 0.f;

    auto prefetch = [&](int ck, int buf){
        uint32_t stage = sb + buf*65536;
#pragma unroll
        for (int it = 0; it < 2; it++){
            int i = tid + it*512;
            int row = i >> 3, g = i & 7;
            uint32_t so = stage + row*128 + (((g ^ (row & 7)) << 4));
            cp16(so,         Ahi + (arow0 + row)*256 + ck*64 + g*8);
            cp16(so + 16384, Alo + (arow0 + row)*256 + ck*64 + g*8);
            cp16(so + 32768, wh + row*256 + ck*64 + g*8);
            cp16(so + 49152, wl + row*256 + ck*64 + g*8);
        }
        cp_commit();
    };

    prefetch(0, 0);

    for (int ck = 0; ck < 4; ck++){
        int buf = ck & 1;
        if (ck + 1 < 4){ prefetch(ck + 1, (ck + 1) & 1); cp_wait<1>(); }
        else           { cp_wait<0>(); }
        __syncthreads();

        uint32_t stage = sb + buf*65536;
#pragma unroll
        for (int k16 = 0; k16 < 4; k16++){
            int msel = lane >> 3;
            int rsub = (msel & 1)*8 + (lane & 7);
            int gg   = k16*2 + (msel >> 1);
            uint32_t ah[2][4], al[2][4];
#pragma unroll
            for (int mi = 0; mi < 2; mi++){
                int r = wm*32 + mi*16 + rsub;
                uint32_t ad = stage + r*128 + (((gg ^ (r & 7)) << 4));
                ldsm4(ah[mi], ad);
                ldsm4(al[mi], ad + 16384);
            }
            uint32_t bh[2][4], bl[2][4];
#pragma unroll
            for (int nj = 0; nj < 2; nj++){
                int r = wn*32 + nj*16 + rsub;
                uint32_t ad = stage + 32768 + r*128 + (((gg ^ (r & 7)) << 4));
                ldsm4(bh[nj], ad);
                ldsm4(bl[nj], ad + 16384);
            }
#pragma unroll
            for (int mi = 0; mi < 2; mi++)
#pragma unroll
                for (int ni = 0; ni < 4; ni++){
                    int nj = ni >> 1, sel = ni & 1;
                    mma16816(acc[mi][ni], ah[mi], bh[nj][sel], bh[nj][2+sel]);
                    mma16816(acc[mi][ni], ah[mi], bl[nj][sel], bl[nj][2+sel]);
                    mma16816(acc[mi][ni], al[mi], bh[nj][sel], bh[nj][2+sel]);
                }
        }
        __syncthreads();
    }

    float* st = reinterpret_cast<float*>(sm);
#pragma unroll
    for (int mi = 0; mi < 2; mi++)
#pragma unroll
        for (int ni = 0; ni < 4; ni++){
            int r0 = wm*32 + mi*16 + (lane >> 2);
            int c0 = wn*32 + ni*8 + (lane & 3)*2;
            *reinterpret_cast<float2*>(st + r0*132 + c0)       = make_float2(acc[mi][ni][0], acc[mi][ni][1]);
            *reinterpret_cast<float2*>(st + (r0 + 8)*132 + c0) = make_float2(acc[mi][ni][2], acc[mi][ni][3]);
        }
    __syncthreads();
    const float4* bp4 = reinterpret_cast<const float4*>(bkv + slot*256 + nh*128);
    float* dst = Cbuf + (size_t)slot*KVSZ + arow0*256 + nh*128;
#pragma unroll
    for (int it = 0; it < 8; it++){
        int i = tid + it*512;
        int row = i >> 5, q = i & 31;
        float4 v = *reinterpret_cast<float4*>(st + row*132 + q*4);
        float4 bb = bp4[q];
        v.x += bb.x; v.y += bb.y; v.z += bb.z; v.w += bb.w;
        *reinterpret_cast<float4*>(dst + (size_t)row*256 + q*4) = v;
    }
}

// ---- mma.sync small GEMM: C[.,N] = A(hi/lo)[.,256] @ Wt(hi/lo)^T (+bias) ----
__global__ void __launch_bounds__(256) k_qgemm(
    const __nv_bfloat16* __restrict__ Ah, const __nv_bfloat16* __restrict__ Al,
    const __nv_bfloat16* __restrict__ Wh, const __nv_bfloat16* __restrict__ Wl,
    const float* __restrict__ bias, float* __restrict__ C, int ldc)
{
    extern __shared__ char sm[];
    uint32_t sb = smem_u32(sm);
    int tid = threadIdx.x, lane = tid & 31, warp = tid >> 5;
    int mt = blockIdx.x, nt = blockIdx.y;
    size_t arow0 = (size_t)mt * 128;
    const __nv_bfloat16* wh = Wh + (size_t)nt*128*256;
    const __nv_bfloat16* wl = Wl + (size_t)nt*128*256;

    int wm = warp >> 1, wn = warp & 1;

    float acc[2][8][4];
#pragma unroll
    for (int mi = 0; mi < 2; mi++)
#pragma unroll
        for (int ni = 0; ni < 8; ni++)
#pragma unroll
            for (int k = 0; k < 4; k++) acc[mi][ni][k] = 0.f;

    auto prefetch = [&](int ck, int buf){
        uint32_t stage = sb + buf*65536;
#pragma unroll
        for (int it = 0; it < 4; it++){
            int i = tid + it*256;
            int row = i >> 3, g = i & 7;
            uint32_t so = stage + row*128 + (((g ^ (row & 7)) << 4));
            cp16(so,         Ah + (arow0 + row)*256 + ck*64 + g*8);
            cp16(so + 16384, Al + (arow0 + row)*256 + ck*64 + g*8);
            cp16(so + 32768, wh + row*256 + ck*64 + g*8);
            cp16(so + 49152, wl + row*256 + ck*64 + g*8);
        }
        cp_commit();
    };

    prefetch(0, 0);

    for (int ck = 0; ck < 4; ck++){
        int buf = ck & 1;
        if (ck + 1 < 4){ prefetch(ck + 1, (ck + 1) & 1); cp_wait<1>(); }
        else           { cp_wait<0>(); }
        __syncthreads();

        uint32_t stage = sb + buf*65536;
#pragma unroll
        for (int k16 = 0; k16 < 4; k16++){
            int msel = lane >> 3;
            int rsub = (msel & 1)*8 + (lane & 7);
            int gg   = k16*2 + (msel >> 1);
            uint32_t ah[2][4], al[2][4];
#pragma unroll
            for (int mi = 0; mi < 2; mi++){
                int r = wm*32 + mi*16 + rsub;
                uint32_t ad = stage + r*128 + (((gg ^ (r & 7)) << 4));
                ldsm4(ah[mi], ad);
                ldsm4(al[mi], ad + 16384);
            }
            uint32_t bh[4][4], bl[4][4];
#pragma unroll
            for (int nj = 0; nj < 4; nj++){
                int r = wn*64 + nj*16 + rsub;
                uint32_t ad = stage + 32768 + r*128 + (((gg ^ (r & 7)) << 4));
                ldsm4(bh[nj], ad);
                ldsm4(bl[nj], ad + 16384);
            }
#pragma unroll
            for (int mi = 0; mi < 2; mi++)
#pragma unroll
                for (int ni = 0; ni < 8; ni++){
                    int nj = ni >> 1, sel = ni & 1;
                    mma16816(acc[mi][ni], ah[mi], bh[nj][sel], bh[nj][2+sel]);
                    mma16816(acc[mi][ni], ah[mi], bl[nj][sel], bl[nj][2+sel]);
                    mma16816(acc[mi][ni], al[mi], bh[nj][sel], bh[nj][2+sel]);
                }
        }
        __syncthreads();
    }

    int n0 = nt*128;
#pragma unroll
    for (int mi = 0; mi < 2; mi++){
#pragma unroll
        for (int ni = 0; ni < 8; ni++){
            int row = (int)arow0 + wm*32 + mi*16 + (lane >> 2);
            int col = n0 + wn*64 + ni*8 + (lane & 3)*2;
            float bx = bias ? bias[col]     : 0.f;
            float by = bias ? bias[col + 1] : 0.f;
            float2 v0 = make_float2(acc[mi][ni][0] + bx, acc[mi][ni][1] + by);
            float2 v1 = make_float2(acc[mi][ni][2] + bx, acc[mi][ni][3] + by);
            *reinterpret_cast<float2*>(C + (size_t)row*ldc + col) = v0;
            *reinterpret_cast<float2*>(C + (size_t)(row + 8)*ldc + col) = v1;
        }
    }
}

// ---- fused: qsa = O@Wsw^T+bsw ; X = LN(qsa) (smem bf16 hi/lo) ; qn = X@Wq'^T+bwq ----
// grid 13, 512 threads, 192KB dynamic smem.
__global__ void __launch_bounds__(512) k_sablock(
    const __nv_bfloat16* __restrict__ Oh, const __nv_bfloat16* __restrict__ Ol,
    const __nv_bfloat16* __restrict__ Wsh, const __nv_bfloat16* __restrict__ Wsl,
    const float* __restrict__ bsw,
    const __nv_bfloat16* __restrict__ Wqh, const __nv_bfloat16* __restrict__ Wql,
    const float* __restrict__ bwq,
    float* __restrict__ qsa, float* __restrict__ qn)
{
    extern __shared__ char sm[];
    __shared__ float psum[128][4], psq[128][4];
    __shared__ float smean[128], srinv[128];
    uint32_t sb = smem_u32(sm);
    int tid = threadIdx.x, lane = tid & 31, warp = tid >> 5;
    int wm = warp >> 2, wn = warp & 3;           // 4m x 4n warps, tile 32x64
    size_t arow0 = (size_t)blockIdx.x * 128;

    float acc[2][8][4];
#pragma unroll
    for (int mi = 0; mi < 2; mi++)
#pragma unroll
        for (int ni = 0; ni < 8; ni++)
#pragma unroll
            for (int k = 0; k < 4; k++) acc[mi][ni][k] = 0.f;

    // ---- GEMM1: double-buffered 96KB stages ----
    auto prefetch1 = [&](int ck, int buf){
        uint32_t stage = sb + buf*98304;
#pragma unroll
        for (int it = 0; it < 2; it++){           // A: 128 rows x 8g
            int i = tid + it*512;
            int row = i >> 3, g = i & 7;
            uint32_t so = stage + row*128 + (((g ^ (row & 7)) << 4));
            cp16(so,         Oh + (arow0 + row)*256 + ck*64 + g*8);
            cp16(so + 16384, Ol + (arow0 + row)*256 + ck*64 + g*8);
        }
#pragma unroll
        for (int it = 0; it < 4; it++){           // B: 256 rows x 8g
            int i = tid + it*512;
            int row = i >> 3, g = i & 7;
            uint32_t so = stage + 32768 + row*128 + (((g ^ (row & 7)) << 4));
            cp16(so,         Wsh + row*256 + ck*64 + g*8);
            cp16(so + 32768, Wsl + row*256 + ck*64 + g*8);
        }
        cp_commit();
    };

    prefetch1(0, 0);
    for (int ck = 0; ck < 4; ck++){
        int buf = ck & 1;
        if (ck + 1 < 4){ prefetch1(ck + 1, (ck + 1) & 1); cp_wait<1>(); }
        else           { cp_wait<0>(); }
        __syncthreads();
        uint32_t stage = sb + buf*98304;
#pragma unroll
        for (int k16 = 0; k16 < 4; k16++){
            int msel = lane >> 3;
            int rsub = (msel & 1)*8 + (lane & 7);
            int gg   = k16*2 + (msel >> 1);
            uint32_t ah[2][4], al[2][4];
#pragma unroll
            for (int mi = 0; mi < 2; mi++){
                int r = wm*32 + mi*16 + rsub;
                uint32_t ad = stage + r*128 + (((gg ^ (r & 7)) << 4));
                ldsm4(ah[mi], ad);
                ldsm4(al[mi], ad + 16384);
            }
            uint32_t bh[4][4], bl[4][4];
#pragma unroll
            for (int nj = 0; nj < 4; nj++){
                int r = wn*64 + nj*16 + rsub;
                uint32_t ad = stage + 32768 + r*128 + (((gg ^ (r & 7)) << 4));
                ldsm4(bh[nj], ad);
                ldsm4(bl[nj], ad + 32768);
            }
#pragma unroll
            for (int mi = 0; mi < 2; mi++)
#pragma unroll
                for (int ni = 0; ni < 8; ni++){
                    int nj = ni >> 1, sel = ni & 1;
                    mma16816(acc[mi][ni], ah[mi], bh[nj][sel], bh[nj][2+sel]);
                    mma16816(acc[mi][ni], ah[mi], bl[nj][sel], bl[nj][2+sel]);
                    mma16816(acc[mi][ni], al[mi], bh[nj][sel], bh[nj][2+sel]);
                }
        }
        __syncthreads();
    }

    // ---- epilogue1: bias + qsa write + LN stats ----
    float s[4] = {0,0,0,0}, sq2[4] = {0,0,0,0};
#pragma unroll
    for (int mi = 0; mi < 2; mi++)
#pragma unroll
        for (int ni = 0; ni < 8; ni++){
            int col = wn*64 + ni*8 + (lane & 3)*2;
            float b0 = bsw[col], b1 = bsw[col+1];
            float v0 = acc[mi][ni][0] + b0, v1 = acc[mi][ni][1] + b1;
            float v2 = acc[mi][ni][2] + b0, v3 = acc[mi][ni][3] + b1;
            int r0 = wm*32 + mi*16 + (lane >> 2);
            *reinterpret_cast<float2*>(qsa + (arow0 + r0)*256 + col)     = make_float2(v0, v1);
            *reinterpret_cast<float2*>(qsa + (arow0 + r0 + 8)*256 + col) = make_float2(v2, v3);
            s[mi*2+0] += v0 + v1; sq2[mi*2+0] += v0*v0 + v1*v1;
            s[mi*2+1] += v2 + v3; sq2[mi*2+1] += v2*v2 + v3*v3;
        }
#pragma unroll
    for (int k = 0; k < 4; k++){
        s[k]   += __shfl_xor_sync(0xffffffffu, s[k], 1);
        s[k]   += __shfl_xor_sync(0xffffffffu, s[k], 2);
        sq2[k] += __shfl_xor_sync(0xffffffffu, sq2[k], 1);
        sq2[k] += __shfl_xor_sync(0xffffffffu, sq2[k], 2);
    }
    if ((lane & 3) == 0){
        int rb = wm*32 + (lane >> 2);
        psum[rb][wn] = s[0];      psq[rb][wn] = sq2[0];
        psum[rb+8][wn] = s[1];    psq[rb+8][wn] = sq2[1];
        psum[rb+16][wn] = s[2];   psq[rb+16][wn] = sq2[2];
        psum[rb+24][wn] = s[3];   psq[rb+24][wn] = sq2[3];
    }
    __syncthreads();
    if (tid < 128){
        float m = (psum[tid][0] + psum[tid][1] + psum[tid][2] + psum[tid][3]) * (1.f/256.f);
        float q2 = (psq[tid][0] + psq[tid][1] + psq[tid][2] + psq[tid][3]) * (1.f/256.f);
        smean[tid] = m;
        srinv[tid] = rsqrtf(q2 - m*m + 1e-5f);
    }
    __syncthreads();

    // ---- write X = LN(qsa) to smem as swizzled bf16 hi/lo ----
    // Xh chunk ck at sb + ck*16384; Xl at sb + 65536 + ck*16384.
#pragma unroll
    for (int mi = 0; mi < 2; mi++)
#pragma unroll
        for (int ni = 0; ni < 8; ni++){
            int col = wn*64 + ni*8 + (lane & 3)*2;
            float b0 = bsw[col], b1 = bsw[col+1];
            int chn = col >> 6, g = (col >> 3) & 7, cb = (col & 7)*2;
#pragma unroll
            for (int half = 0; half < 2; half++){
                int r = wm*32 + mi*16 + (lane >> 2) + half*8;
                float m = smean[r], ri = srinv[r];
                float x0 = (acc[mi][ni][half*2+0] + b0 - m)*ri;
                float x1 = (acc[mi][ni][half*2+1] + b1 - m)*ri;
                uint32_t off = chn*16384 + r*128 + ((g ^ (r & 7)) << 4) + cb;
                __nv_bfloat16 h0 = __float2bfloat16(x0);
                __nv_bfloat16 h1 = __float2bfloat16(x1);
                float l0 = x0 - __bfloat162float(h0);
                float l1 = x1 - __bfloat162float(h1);
                *reinterpret_cast<uint32_t*>(sm + off) = pack2(x0, x1);
                *reinterpret_cast<uint32_t*>(sm + 65536 + off) = pack2(l0, l1);
            }
        }
    __syncthreads();

    // ---- GEMM2: qn = X @ Wq'^T + bwq, B single-buffered at sb+131072 ----
#pragma unroll
    for (int mi = 0; mi < 2; mi++)
#pragma unroll
        for (int ni = 0; ni < 8; ni++)
#pragma unroll
            for (int k = 0; k < 4; k++) acc[mi][ni][k] = 0.f;

    for (int ck = 0; ck < 4; ck++){
#pragma unroll
        for (int it = 0; it < 4; it++){
            int i = tid + it*512;
            int row = i >> 3, g = i & 7;
            uint32_t so = sb + 131072 + row*128 + (((g ^ (row & 7)) << 4));
            cp16(so,         Wqh + row*256 + ck*64 + g*8);
            cp16(so + 32768, Wql + row*256 + ck*64 + g*8);
        }
        cp_commit();
        cp_wait<0>();
        __syncthreads();
#pragma unroll
        for (int k16 = 0; k16 < 4; k16++){
            int msel = lane >> 3;
            int rsub = (msel & 1)*8 + (lane & 7);
            int gg   = k16*2 + (msel >> 1);
            uint32_t ah[2][4], al[2][4];
#pragma unroll
            for (int mi = 0; mi < 2; mi++){
                int r = wm*32 + mi*16 + rsub;
                uint32_t ad = sb + ck*16384 + r*128 + (((gg ^ (r & 7)) << 4));
                ldsm4(ah[mi], ad);
                ldsm4(al[mi], ad + 65536);
            }
            uint32_t bh[4][4], bl[4][4];
#pragma unroll
            for (int nj = 0; nj < 4; nj++){
                int r = wn*64 + nj*16 + rsub;
                uint32_t ad = sb + 131072 + r*128 + (((gg ^ (r & 7)) << 4));
                ldsm4(bh[nj], ad);
                ldsm4(bl[nj], ad + 32768);
            }
#pragma unroll
            for (int mi = 0; mi < 2; mi++)
#pragma unroll
                for (int ni = 0; ni < 8; ni++){
                    int nj = ni >> 1, sel = ni & 1;
                    mma16816(acc[mi][ni], ah[mi], bh[nj][sel], bh[nj][2+sel]);
                    mma16816(acc[mi][ni], ah[mi], bl[nj][sel], bl[nj][2+sel]);
                    mma16816(acc[mi][ni], al[mi], bh[nj][sel], bh[nj][2+sel]);
                }
        }
        __syncthreads();
    }
#pragma unroll
    for (int mi = 0; mi < 2; mi++)
#pragma unroll
        for (int ni = 0; ni < 8; ni++){
            int col = wn*64 + ni*8 + (lane & 3)*2;
            float b0 = bwq[col], b1 = bwq[col+1];
            int r0 = wm*32 + mi*16 + (lane >> 2);
            *reinterpret_cast<float2*>(qn + (arow0 + r0)*256 + col) =
                make_float2(acc[mi][ni][0] + b0, acc[mi][ni][1] + b1);
            *reinterpret_cast<float2*>(qn + (arow0 + r0 + 8)*256 + col) =
                make_float2(acc[mi][ni][2] + b0, acc[mi][ni][3] + b1);
        }
}

// ---------------- self-attention over 100 keys, per (h, b, l) ----------------
__global__ void __launch_bounds__(128) k_sa(const float* __restrict__ qkv,
                                            __nv_bfloat16* __restrict__ oh,
                                            __nv_bfloat16* __restrict__ ol){
    __shared__ __align__(16) float sK[100][32];
    __shared__ __align__(16) float sV[100][32];
    int h = blockIdx.x, b = blockIdx.y, l = blockIdx.z;
    int lb = l*4 + b;
    const float* qb = qkv + (size_t)lb*100*768;
    for (int idx = threadIdx.x; idx < 1600; idx += 128){
        int arr = (idx >= 800);
        int rem = arr ? idx - 800 : idx;
        int row = rem >> 3, qd = rem & 7;
        float4 v = *reinterpret_cast<const float4*>(
            qb + (size_t)row*768 + 256 + arr*256 + h*32 + qd*4);
        float* dstp = arr ? &sV[row][qd*4] : &sK[row][qd*4];
        *reinterpret_cast<float4*>(dstp) = v;
    }
    __syncthreads();
    int i = threadIdx.x;
    if (i < 100){
        float Q[32];
        const float4* qp4 = reinterpret_cast<const float4*>(qb + (size_t)i*768 + h*32);
#pragma unroll
        for (int qd = 0; qd < 8; qd++){
            float4 v = qp4[qd];
            Q[qd*4+0] = v.x; Q[qd*4+1] = v.y; Q[qd*4+2] = v.z; Q[qd*4+3] = v.w;
        }
        float m = -1e30f, scale = 0.f, acc[32];
#pragma unroll
        for (int c = 0; c < 32; c++) acc[c] = 0.f;
        for (int j = 0; j < 100; j++){
            const float4* k4 = reinterpret_cast<const float4*>(sK[j]);
            float d = 0.f;
#pragma unroll
            for (int qd = 0; qd < 8; qd++){
                float4 kv = k4[qd];
                d = fmaf(Q[qd*4+0], kv.x, d); d = fmaf(Q[qd*4+1], kv.y, d);
                d = fmaf(Q[qd*4+2], kv.z, d); d = fmaf(Q[qd*4+3], kv.w, d);
            }
            d *= 0.17677669529663687f;
            const float4* v4 = reinterpret_cast<const float4*>(sV[j]);
            if (d > m){
                float f = __expf(m - d);
                m = d; scale = fmaf(scale, f, 1.f);
#pragma unroll
                for (int qd = 0; qd < 8; qd++){
                    float4 vv = v4[qd];
                    acc[qd*4+0] = fmaf(acc[qd*4+0], f, vv.x);
                    acc[qd*4+1] = fmaf(acc[qd*4+1], f, vv.y);
                    acc[qd*4+2] = fmaf(acc[qd*4+2], f, vv.z);
                    acc[qd*4+3] = fmaf(acc[qd*4+3], f, vv.w);
                }
            } else {
                float p = __expf(d - m);
                scale += p;
#pragma unroll
                for (int qd = 0; qd < 8; qd++){
                    float4 vv = v4[qd];
                    acc[qd*4+0] = fmaf(p, vv.x, acc[qd*4+0]);
                    acc[qd*4+1] = fmaf(p, vv.y, acc[qd*4+1]);
                    acc[qd*4+2] = fmaf(p, vv.z, acc[qd*4+2]);
                    acc[qd*4+3] = fmaf(p, vv.w, acc[qd*4+3]);
                }
            }
        }
        float inv = 1.f / scale;
        size_t ob = (size_t)(lb*100 + i)*256 + h*32;
#pragma unroll
        for (int c = 0; c < 32; c++)
            hilo(acc[c]*inv, &oh[ob + c], &ol[ob + c]);
    }
}

// ---------------- cross-attention flash partials ----------------
__global__ void __launch_bounds__(128) k_cross(
    const float* __restrict__ qn, const float* __restrict__ Kg,
    const float* __restrict__ Vg, float* __restrict__ pm,
    float* __restrict__ ps, float* __restrict__ pacc)
{
    __shared__ __align__(16) float sKV[2][2][64][32];
    int ss = blockIdx.x, h = blockIdx.y, vb = blockIdx.z;
    int v = vb >> 2, b = vb & 3;
    int l = c_sl[ss];
    int Nl = c_N[l];
    int ck = c_ck[ss];
    int kbeg = c_sk[ss]*ck;
    int lb = l*4 + b;
    size_t kvbase = ((size_t)v*TOKV + c_off[l] + (size_t)b*Nl)*256 + h*32;
    const float* Kp = Kg + kvbase;
    const float* Vp = Vg + kvbase;
    int tid = threadIdx.x;
    uint32_t sbase = smem_u32(&sKV[0][0][0][0]);

    auto prefetch = [&](int kc, int buf){
        uint32_t stage = sbase + buf*16384;
#pragma unroll
        for (int it = 0; it < 8; it++){
            int idx = tid + it*128;
            int a = idx >> 9, rem = idx & 511;
            int row = rem >> 3, qd = rem & 7;
            const float* src = (a ? Vp : Kp) + (size_t)(kc + row)*256 + qd*4;
            cp16(stage + a*8192 + row*128 + qd*16, src);
        }
        cp_commit();
    };

    int i = tid;
    float Q[32];
    if (i < 100){
        const float4* qp4 = reinterpret_cast<const float4*>(
            qn + (size_t)(lb*100 + i)*256 + h*32);
#pragma unroll
        for (int qd = 0; qd < 8; qd++){
            float4 vq = qp4[qd];
            Q[qd*4+0] = vq.x; Q[qd*4+1] = vq.y; Q[qd*4+2] = vq.z; Q[qd*4+3] = vq.w;
        }
    }
    float m = -1e30f, s = 0.f, acc[32];
#pragma unroll
    for (int c = 0; c < 32; c++) acc[c] = 0.f;

    int nchunks = ck >> 6;
    prefetch(kbeg, 0);
    for (int cki = 0; cki < nchunks; cki++){
        int buf = cki & 1;
        if (cki + 1 < nchunks){ prefetch(kbeg + (cki+1)*64, buf ^ 1); cp_wait<1>(); }
        else                  { cp_wait<0>(); }
        __syncthreads();
        if (i < 100){
            for (int j = 0; j < 64; j++){
                const float4* k4 = reinterpret_cast<const float4*>(sKV[buf][0][j]);
                float d = 0.f;
#pragma unroll
                for (int qd = 0; qd < 8; qd++){
                    float4 kv = k4[qd];
                    d = fmaf(Q[qd*4+0], kv.x, d); d = fmaf(Q[qd*4+1], kv.y, d);
                    d = fmaf(Q[qd*4+2], kv.z, d); d = fmaf(Q[qd*4+3], kv.w, d);
                }
                d *= 0.17677669529663687f;
                const float4* v4 = reinterpret_cast<const float4*>(sKV[buf][1][j]);
                if (d > m){
                    float f = __expf(m - d);
                    m = d; s = fmaf(s, f, 1.f);
#pragma unroll
                    for (int qd = 0; qd < 8; qd++){
                        float4 vv = v4[qd];
                        acc[qd*4+0] = fmaf(acc[qd*4+0], f, vv.x);
                        acc[qd*4+1] = fmaf(acc[qd*4+1], f, vv.y);
                        acc[qd*4+2] = fmaf(acc[qd*4+2], f, vv.z);
                        acc[qd*4+3] = fmaf(acc[qd*4+3], f, vv.w);
                    }
                } else {
                    float p = __expf(d - m);
                    s += p;
#pragma unroll
                    for (int qd = 0; qd < 8; qd++){
                        float4 vv = v4[qd];
                        acc[qd*4+0] = fmaf(p, vv.x, acc[qd*4+0]);
                        acc[qd*4+1] = fmaf(p, vv.y, acc[qd*4+1]);
                        acc[qd*4+2] = fmaf(p, vv.z, acc[qd*4+2]);
                        acc[qd*4+3] = fmaf(p, vv.w, acc[qd*4+3]);
                    }
                }
            }
        }
        __syncthreads();
    }
    if (i < 100){
        int slot = (vb*8 + h)*22 + ss;
        pm[slot*100 + i] = m;
        ps[slot*100 + i] = s;
        float* pa = pacc + (size_t)(slot*100 + i)*32;
#pragma unroll
        for (int c = 0; c < 32; c++) pa[c] = acc[c];
    }
}

__global__ void __launch_bounds__(128) k_combine(
    const float* __restrict__ pm, const float* __restrict__ ps,
    const float* __restrict__ pacc,
    __nv_bfloat16* __restrict__ och, __nv_bfloat16* __restrict__ ocl)
{
    int l = blockIdx.x, h = blockIdx.y, vb = blockIdx.z;
    int i = threadIdx.x;
    if (i >= 100) return;
    int S = c_S[l], s0 = c_s0[l];
    int base = (vb*8 + h)*22 + s0;
    float M = -1e30f;
    for (int k = 0; k < S; k++) M = fmaxf(M, pm[(base + k)*100 + i]);
    float Ss = 0.f, acc[32];
#pragma unroll
    for (int c = 0; c < 32; c++) acc[c] = 0.f;
    for (int k = 0; k < S; k++){
        int slot = base + k;
        float f = __expf(pm[slot*100 + i] - M);
        Ss = fmaf(ps[slot*100 + i], f, Ss);
        const float* pa = pacc + (size_t)(slot*100 + i)*32;
#pragma unroll
        for (int c = 0; c < 32; c++) acc[c] = fmaf(pa[c], f, acc[c]);
    }
    float inv = 1.f / Ss;
    int v = vb >> 2, b = vb & 3;
    int lb = l*4 + b;
    size_t ob = (size_t)(v*1600 + lb*100 + i)*256 + h*32;
#pragma unroll
    for (int c = 0; c < 32; c++)
        hilo(acc[c]*inv, &och[ob + c], &ocl[ob + c]);
}

// ---- match + softmaxes + fuse + channel softmax, one block per lb ----
__global__ void __launch_bounds__(256) k_matchfuse(
    const float* __restrict__ q12, const float* __restrict__ qsa,
    __nv_bfloat16* __restrict__ qh, __nv_bfloat16* __restrict__ ql,
    float* __restrict__ outp)
{
    extern __shared__ float buf[];          // ms 10100 | swr @10112 (10000) | swc @20112 (10000)
    float* swr = buf + 10112;
    float* swc = buf + 20112;
    float* sA  = buf + 10112;               // phase-A overlay (3300)
    float* sB  = buf + 13412;               // phase-A overlay (3300)
    int lb = blockIdx.x;
    int tid = threadIdx.x;
    int lane = tid & 31, w = tid >> 5;
    const float* q1 = q12 + (size_t)lb*25600;
    const float* q2 = q12 + 409600 + (size_t)lb*25600;

    // ---- phase A: ms = q1 @ q2^T ----
    {
        int tx = tid & 15, ty = tid >> 4;
        float acc[7][7];
#pragma unroll
        for (int a = 0; a < 7; a++)
#pragma unroll
            for (int bq = 0; bq < 7; bq++) acc[a][bq] = 0.f;
        for (int k0 = 0; k0 < 256; k0 += 32){
            __syncthreads();
            for (int idx = tid; idx < 3200; idx += 256){
                int r = idx >> 5, kk = idx & 31;
                sA[r*33 + kk] = q1[(size_t)r*256 + k0 + kk];
                sB[r*33 + kk] = q2[(size_t)r*256 + k0 + kk];
            }
            __syncthreads();
            for (int kk = 0; kk < 32; kk++){
                float a[7], b[7];
#pragma unroll
                for (int ii = 0; ii < 7; ii++){
                    int i = ty + 16*ii;
                    a[ii] = (i < 100) ? sA[i*33 + kk] : 0.f;
                }
#pragma unroll
                for (int jj = 0; jj < 7; jj++){
                    int j = tx + 16*jj;
                    b[jj] = (j < 100) ? sB[j*33 + kk] : 0.f;
                }
#pragma unroll
                for (int ii = 0; ii < 7; ii++)
#pragma unroll
                    for (int jj = 0; jj < 7; jj++) acc[ii][jj] = fmaf(a[ii], b[jj], acc[ii][jj]);
            }
        }
        __syncthreads();
#pragma unroll
        for (int ii = 0; ii < 7; ii++){
            int i = ty + 16*ii;
            if (i < 100){
#pragma unroll
                for (int jj = 0; jj < 7; jj++){
                    int j = tx + 16*jj;
                    if (j < 100) buf[i*101 + j] = acc[ii][jj];
                }
            }
        }
        __syncthreads();
    }

    // ---- phase B: row softmax -> swr[i*100+j]; col softmax -> swc[j*100+i] ----
    for (int r = w; r < 100; r += 8){
        float v0 = buf[r*101 + lane];
        float v1 = buf[r*101 + 32 + lane];
        float v2 = buf[r*101 + 64 + lane];
        float v3 = (lane < 4) ? buf[r*101 + 96 + lane] : -1e30f;
        float M = warpMax(fmaxf(fmaxf(v0, v1), fmaxf(v2, v3)));
        float p0 = __expf(v0 - M), p1 = __expf(v1 - M), p2 = __expf(v2 - M);
        float p3 = (lane < 4) ? __expf(v3 - M) : 0.f;
        float S = warpSum(p0 + p1 + p2 + p3);
        float inv = 1.f / S;
        swr[r*100 + lane] = p0*inv; swr[r*100 + 32 + lane] = p1*inv;
        swr[r*100 + 64 + lane] = p2*inv;
        if (lane < 4) swr[r*100 + 96 + lane] = p3*inv;
    }
    for (int cc = w; cc < 100; cc += 8){
        float v0 = buf[lane*101 + cc];
        float v1 = buf[(32 + lane)*101 + cc];
        float v2 = buf[(64 + lane)*101 + cc];
        float v3 = (lane < 4) ? buf[(96 + lane)*101 + cc] : -1e30f;
        float M = warpMax(fmaxf(fmaxf(v0, v1), fmaxf(v2, v3)));
        float p0 = __expf(v0 - M), p1 = __expf(v1 - M), p2 = __expf(v2 - M);
        float p3 = (lane < 4) ? __expf(v3 - M) : 0.f;
        float S = warpSum(p0 + p1 + p2 + p3);
        float inv = 1.f / S;
        swc[lane*100 + cc] = p0*inv; swc[(32 + lane)*100 + cc] = p1*inv;
        swc[(64 + lane)*100 + cc] = p2*inv;
        if (lane < 4) swc[(96 + lane)*100 + cc] = p3*inv;
    }
    __syncthreads();

    // ---- phase C: fuse + channel softmax (warp-per-row-group) ----
    for (int i0 = w*4; i0 < 100; i0 += 32){
        float acc[4][8];
#pragma unroll
        for (int r = 0; r < 4; r++){
            int i = i0 + r;
#pragma unroll
            for (int k = 0; k < 8; k++){
                int c = lane + 32*k;
                acc[r][k] = qsa[(size_t)(lb*100 + i)*256 + c]
                          + q1[(size_t)i*256 + c] + q2[(size_t)i*256 + c];
            }
        }
        for (int j = 0; j < 100; j++){
            float q1v[8], q2v[8];
#pragma unroll
            for (int k = 0; k < 8; k++){
                int c = lane + 32*k;
                q1v[k] = q1[(size_t)j*256 + c];
                q2v[k] = q2[(size_t)j*256 + c];
            }
#pragma unroll
            for (int r = 0; r < 4; r++){
                int i = i0 + r;
                float wrv = swr[i*100 + j];
                float wcv = swc[j*100 + i];
#pragma unroll
                for (int k = 0; k < 8; k++)
                    acc[r][k] += wrv*q2v[k] + wcv*q1v[k];
            }
        }
#pragma unroll
        for (int r = 0; r < 4; r++){
            int i = i0 + r;
            float mx = -1e30f;
#pragma unroll
            for (int k = 0; k < 8; k++) mx = fmaxf(mx, acc[r][k]);
            mx = warpMax(mx);
            float e[8], sum = 0.f;
#pragma unroll
            for (int k = 0; k < 8; k++){ e[k] = __expf(acc[r][k] - mx); sum += e[k]; }
            sum = warpSum(sum);
            float inv = 1.f / sum;
            size_t base = (size_t)(lb*100 + i)*256;
#pragma unroll
            for (int k = 0; k < 8; k++){
                int c = lane + 32*k;
                float val = e[k]*inv;
                if (outp) outp[base + c] = val;
                else      hilo(val, &qh[base + c], &ql[base + c]);
            }
        }
    }
}

// ---------------- host ----------------
extern "C" void kernel_launch(void* const* d_in, const int* in_sizes, int n_in,
                              void* d_out, int out_size)
{
    float* arena;   cudaGetSymbolAddress((void**)&arena, g_buf);
    float* kvbuf;   cudaGetSymbolAddress((void**)&kvbuf, g_kv);
    __nv_bfloat16 *ahi, *alo, *whi, *wlo;
    cudaGetSymbolAddress((void**)&ahi, g_ahi);
    cudaGetSymbolAddress((void**)&alo, g_alo);
    cudaGetSymbolAddress((void**)&whi, g_whi);
    cudaGetSymbolAddress((void**)&wlo, g_wlo);
    float* bkv;     cudaGetSymbolAddress((void**)&bkv, g_bkv);
    __nv_bfloat16 *qh, *ql, *oh, *ol, *och, *ocl;
    cudaGetSymbolAddress((void**)&qh, g_qh);   cudaGetSymbolAddress((void**)&ql, g_ql);
    cudaGetSymbolAddress((void**)&oh, g_oh);   cudaGetSymbolAddress((void**)&ol, g_ol);
    cudaGetSymbolAddress((void**)&och, g_och); cudaGetSymbolAddress((void**)&ocl, g_ocl);
    __nv_bfloat16 *wqkvh, *wqkvl, *wswh, *wswl, *wqh2, *wql2, *wph, *wpl;
    cudaGetSymbolAddress((void**)&wqkvh, g_wqkvh); cudaGetSymbolAddress((void**)&wqkvl, g_wqkvl);
    cudaGetSymbolAddress((void**)&wswh, g_wswh);   cudaGetSymbolAddress((void**)&wswl, g_wswl);
    cudaGetSymbolAddress((void**)&wqh2, g_wqh);    cudaGetSymbolAddress((void**)&wql2, g_wql);
    cudaGetSymbolAddress((void**)&wph, g_wph);     cudaGetSymbolAddress((void**)&wpl, g_wpl);
    float *bsw, *bwq, *bwp;
    cudaGetSymbolAddress((void**)&bsw, g_bsw);
    cudaGetSymbolAddress((void**)&bwq, g_bwq);
    cudaGetSymbolAddress((void**)&bwp, g_bwp);

    float* qkv  = arena;                 // 1,277,952
    float* qsa  = arena + 1277952;       // 425,984
    float* qn   = arena + 1703936;       // 425,984
    float* q12  = arena + 2129920;       // 819,200
    float* pm   = arena + 2949120;       // 140,800
    float* ps   = arena + 3089920;       // 140,800
    float* pacc = arena + 3230720;       // 4,505,600

    FeatPtrs fp;
    for (int i = 0; i < 8; i++) fp.p[i] = (const float*)d_in[i];
    const float* qe   = (const float*)d_in[8];
    const float* ng   = (const float*)d_in[9];
    const float* nb   = (const float*)d_in[10];
    const float* wq   = (const float*)d_in[11];
    const float* wk   = (const float*)d_in[12];
    const float* wv   = (const float*)d_in[13];
    const float* wp   = (const float*)d_in[14];
    const float* bp   = (const float*)d_in[15];
    const float* wqkv = (const float*)d_in[16];
    const float* swp  = (const float*)d_in[17];
    const float* sbp  = (const float*)d_in[18];

    cudaFuncSetAttribute(k_kvgemm,    cudaFuncAttributeMaxDynamicSharedMemorySize, 131072);
    cudaFuncSetAttribute(k_qgemm,     cudaFuncAttributeMaxDynamicSharedMemorySize, 131072);
    cudaFuncSetAttribute(k_sablock,   cudaFuncAttributeMaxDynamicSharedMemorySize, 196608);
    cudaFuncSetAttribute(k_matchfuse, cudaFuncAttributeMaxDynamicSharedMemorySize, 120448);

    k_init_q<<<1600, 256>>>(qe, qh, ql);
    k_tok_ln<<<dim3(680, 2), 256>>>(fp, ahi, alo);
    k_prep_w<<<12, 256>>>(wk, wv, ng, nb, whi, wlo, bkv);
    k_kvgemm<<<dim3(340, 2, 12), 512, 131072>>>(ahi, alo, whi, wlo, bkv, kvbuf); // profiled
    k_prep_wt<<<dim3(3, 6), 256>>>(wqkv, nullptr, nullptr, nullptr, wqkvh, wqkvl, nullptr, 768);
    k_prep_wt<<<dim3(1, 6), 256>>>(swp, nullptr, nullptr, sbp, wswh, wswl, bsw, 256);
    k_prep_wt<<<dim3(1, 6), 256>>>(wq, ng, nb, nullptr, wqh2, wql2, bwq, 256);
    k_prep_wt<<<dim3(1, 6), 256>>>(wp, nullptr, nullptr, bp, wph, wpl, bwp, 256);

    for (int d = 0; d < 6; d++){
        k_qgemm<<<dim3(13, 6), 256, 131072>>>(qh, ql,
            wqkvh + (size_t)d*768*256, wqkvl + (size_t)d*768*256,
            nullptr, qkv, 768);
        k_sa<<<dim3(8, 4, 4), 128>>>(qkv, oh, ol);
        k_sablock<<<13, 512, 196608>>>(oh, ol,
            wswh + (size_t)d*65536, wswl + (size_t)d*65536, bsw + d*256,
            wqh2 + (size_t)d*65536, wql2 + (size_t)d*65536, bwq + d*256,
            qsa, qn);
        k_cross<<<dim3(22, 8, 8), 128>>>(qn, kvbuf + (size_t)(2*d)*KVSZ,
                                         kvbuf + (size_t)(2*d+1)*KVSZ, pm, ps, pacc);
        k_combine<<<dim3(4, 8, 8), 128>>>(pm, ps, pacc, och, ocl);
        k_qgemm<<<dim3(25, 2), 256, 131072>>>(och, ocl,
            wph + (size_t)d*65536, wpl + (size_t)d*65536,
            bwp + d*256, q12, 256);
        k_matchfuse<<<16, 256, 120448>>>(q12, qsa, qh, ql,
                                         (d == 5) ? (float*)d_out : nullptr);
    }
}

// round 13
// speedup vs baseline: 1.3256x; 1.3256x over previous
#include <cuda_runtime.h>
#include <cuda_bf16.h>
#include <cstdint>
#include <math.h>

#define TOKV 21760            // per-view feature tokens: 4*(4096+1024+256+64)
#define AROWS 43520           // 2 views
#define KVSZ  11141120        // 43520*256
#define MPAD  1664            // 1600 padded to 13*128

__constant__ int c_N[4]   = {4096, 1024, 256, 64};
__constant__ int c_off[4] = {0, 16384, 20480, 21504};
// 22 cross-attn split slots (256-key chunks; level 3 has 64)
__constant__ int c_sl[22] = {0,0,0,0,0,0,0,0,0,0,0,0,0,0,0,0, 1,1,1,1, 2, 3};
__constant__ int c_sk[22] = {0,1,2,3,4,5,6,7,8,9,10,11,12,13,14,15, 0,1,2,3, 0, 0};
__constant__ int c_ck[22] = {256,256,256,256,256,256,256,256,256,256,256,256,256,256,256,256,
                             256,256,256,256, 256, 64};
__constant__ int c_S[4]  = {16,4,1,1};
__constant__ int c_s0[4] = {0,16,20,21};

// ---- device scratch (allocations forbidden) ----
__device__ float g_kv[12*KVSZ];
__device__ __nv_bfloat16 g_ahi[AROWS*256];
__device__ __nv_bfloat16 g_alo[AROWS*256];
__device__ __nv_bfloat16 g_whi[12*256*256];
__device__ __nv_bfloat16 g_wlo[12*256*256];
__device__ float g_bkv[12*256];
__device__ __nv_bfloat16 g_qh[MPAD*256],  g_ql[MPAD*256];
__device__ __nv_bfloat16 g_oh[MPAD*256],  g_ol[MPAD*256];
__device__ __nv_bfloat16 g_xh[MPAD*256],  g_xl[MPAD*256];
__device__ __nv_bfloat16 g_och[3200*256], g_ocl[3200*256];
__device__ __nv_bfloat16 g_wqkvh[6*768*256], g_wqkvl[6*768*256];
__device__ __nv_bfloat16 g_wswh[6*256*256],  g_wswl[6*256*256];
__device__ __nv_bfloat16 g_wqh[6*256*256],   g_wql[6*256*256];
__device__ __nv_bfloat16 g_wph[6*256*256],   g_wpl[6*256*256];
__device__ float g_bsw[1536], g_bwq[1536], g_bwp[1536];
__device__ float g_buf[9000000];

struct FeatPtrs { const float* p[8]; };

// ---------------- PTX helpers ----------------
__device__ __forceinline__ uint32_t smem_u32(const void* p){
    uint32_t a;
    asm("{ .reg .u64 t; cvta.to.shared.u64 t, %1; cvt.u32.u64 %0, t; }" : "=r"(a) : "l"(p));
    return a;
}
__device__ __forceinline__ void cp16(uint32_t s, const void* g){
    asm volatile("cp.async.cg.shared.global [%0], [%1], 16;" :: "r"(s), "l"(g) : "memory");
}
__device__ __forceinline__ void cp_commit(){
    asm volatile("cp.async.commit_group;" ::: "memory");
}
template<int N>
__device__ __forceinline__ void cp_wait(){
    asm volatile("cp.async.wait_group %0;" :: "n"(N) : "memory");
}
__device__ __forceinline__ void ldsm4(uint32_t* r, uint32_t a){
    asm volatile("ldmatrix.sync.aligned.m8n8.x4.shared.b16 {%0,%1,%2,%3}, [%4];"
                 : "=r"(r[0]), "=r"(r[1]), "=r"(r[2]), "=r"(r[3]) : "r"(a));
}
__device__ __forceinline__ void mma16816(float* c, const uint32_t* a,
                                         uint32_t b0, uint32_t b1){
    asm volatile(
        "mma.sync.aligned.m16n8k16.row.col.f32.bf16.bf16.f32 "
        "{%0,%1,%2,%3}, {%4,%5,%6,%7}, {%8,%9}, {%0,%1,%2,%3};"
        : "+f"(c[0]), "+f"(c[1]), "+f"(c[2]), "+f"(c[3])
        : "r"(a[0]), "r"(a[1]), "r"(a[2]), "r"(a[3]), "r"(b0), "r"(b1));
}
__device__ __forceinline__ void hilo(float v, __nv_bfloat16* ph, __nv_bfloat16* pl){
    __nv_bfloat16 h = __float2bfloat16(v);
    *ph = h;
    *pl = __float2bfloat16(v - __bfloat162float(h));
}

// ---------------- reductions ----------------
__device__ __forceinline__ float warpSum(float v){
#pragma unroll
    for (int o = 16; o > 0; o >>= 1) v += __shfl_xor_sync(0xffffffffu, v, o);
    return v;
}
__device__ __forceinline__ float warpMax(float v){
#pragma unroll
    for (int o = 16; o > 0; o >>= 1) v = fmaxf(v, __shfl_xor_sync(0xffffffffu, v, o));
    return v;
}
__device__ __forceinline__ float blockSum(float v, float* sh){
    int lane = threadIdx.x & 31, w = threadIdx.x >> 5;
    int nw = blockDim.x >> 5;
    __syncthreads();
    v = warpSum(v);
    if (lane == 0) sh[w] = v;
    __syncthreads();
    if (w == 0){
        float r = (threadIdx.x < nw) ? sh[threadIdx.x] : 0.f;
        r = warpSum(r);
        if (lane == 0) sh[0] = r;
    }
    __syncthreads();
    return sh[0];
}
__device__ __forceinline__ float blockMax(float v, float* sh){
    int lane = threadIdx.x & 31, w = threadIdx.x >> 5;
    int nw = blockDim.x >> 5;
    __syncthreads();
    v = warpMax(v);
    if (lane == 0) sh[w] = v;
    __syncthreads();
    if (w == 0){
        float r = (threadIdx.x < nw) ? sh[threadIdx.x] : -1e30f;
        r = warpMax(r);
        if (lane == 0) sh[0] = r;
    }
    __syncthreads();
    return sh[0];
}

// ---- tokenize + LN normalization -> bf16 hi/lo ----
__global__ void __launch_bounds__(256) k_tok_ln(FeatPtrs fp,
    __nv_bfloat16* __restrict__ ahi, __nv_bfloat16* __restrict__ alo)
{
    __shared__ float s[256][33];
    __shared__ float ps[8][32], pq[8][32];
    __shared__ float mean[32], rinv[32];
    int r = blockIdx.x, v = blockIdx.y;
    int l = (r < 512) ? 0 : (r < 640) ? 1 : (r < 672) ? 2 : 3;
    int off32 = (l == 0) ? 0 : (l == 1) ? 512 : (l == 2) ? 640 : 672;
    int Nl = c_N[l];
    int idx = r - off32;
    int tpb = Nl >> 5;
    int b = idx / tpb, t0 = (idx % tpb) * 32;
    const float* f = fp.p[v*4 + l];
    int g = threadIdx.x >> 5, t = threadIdx.x & 31;
    for (int cc = g; cc < 256; cc += 8)
        s[cc][t] = f[((size_t)(b*256 + cc))*Nl + t0 + t];
    __syncthreads();
    float sx = 0.f, sq = 0.f;
#pragma unroll
    for (int k = 0; k < 32; k++){
        float x = s[g*32 + k][t];
        sx += x; sq = fmaf(x, x, sq);
    }
    ps[g][t] = sx; pq[g][t] = sq;
    __syncthreads();
    if (threadIdx.x < 32){
        float m = 0.f, qq = 0.f;
#pragma unroll
        for (int gg = 0; gg < 8; gg++){ m += ps[gg][threadIdx.x]; qq += pq[gg][threadIdx.x]; }
        m *= (1.f/256.f);
        float var = qq*(1.f/256.f) - m*m;
        mean[threadIdx.x] = m;
        rinv[threadIdx.x] = rsqrtf(var + 1e-5f);
    }
    __syncthreads();
    int c = threadIdx.x;
    size_t rowbase = (size_t)v*TOKV + c_off[l] + (size_t)b*Nl + t0;
    for (int tt = 0; tt < 32; tt++){
        float val = (s[c][tt] - mean[tt]) * rinv[tt];
        hilo(val, &ahi[(rowbase + tt)*256 + c], &alo[(rowbase + tt)*256 + c]);
    }
}

// ---- prep KV weights: Wt[n][k] = g[k]*W[k][n] bf16 hi/lo; bias'[n] = b@W ----
__global__ void __launch_bounds__(256) k_prep_w(
    const float* __restrict__ wk, const float* __restrict__ wv,
    const float* __restrict__ ng, const float* __restrict__ nb,
    __nv_bfloat16* __restrict__ whi, __nv_bfloat16* __restrict__ wlo,
    float* __restrict__ bkv)
{
    int s = blockIdx.x, n = threadIdx.x;
    int d = s >> 1;
    const float* W = ((s & 1) ? wv : wk) + (size_t)d*65536;
    const float* g = ng + d*256;
    const float* b = nb + d*256;
    float bias = 0.f;
    size_t obase = ((size_t)s*256 + n)*256;
    for (int k = 0; k < 256; k++){
        float w0 = W[k*256 + n];
        bias = fmaf(b[k], w0, bias);
        float w = g[k]*w0;
        hilo(w, &whi[obase + k], &wlo[obase + k]);
    }
    bkv[s*256 + n] = bias;
}

// ---- generic weight prep ----
__global__ void __launch_bounds__(256) k_prep_wt(
    const float* __restrict__ W, const float* __restrict__ g,
    const float* __restrict__ bf, const float* __restrict__ ab,
    __nv_bfloat16* __restrict__ wh, __nv_bfloat16* __restrict__ wl,
    float* __restrict__ bo, int N)
{
    int d = blockIdx.y;
    int n = blockIdx.x*256 + threadIdx.x;
    const float* Wd = W + (size_t)d*256*N;
    float bias = ab ? ab[(size_t)d*N + n] : 0.f;
    size_t ob = ((size_t)d*N + n)*256;
    for (int k = 0; k < 256; k++){
        float w0 = Wd[(size_t)k*N + n];
        if (bf) bias = fmaf(bf[d*256 + k], w0, bias);
        float w = g ? g[d*256 + k]*w0 : w0;
        hilo(w, &wh[ob + k], &wl[ob + k]);
    }
    if (bo) bo[(size_t)d*N + n] = bias;
}

__global__ void k_init_q(const float* __restrict__ qe,
                         __nv_bfloat16* __restrict__ qh,
                         __nv_bfloat16* __restrict__ ql){
    int row = blockIdx.x, c = threadIdx.x;
    float val = qe[(row % 100)*256 + c];
    hilo(val, &qh[(size_t)row*256 + c], &ql[(size_t)row*256 + c]);
}

// ---- mma.sync KV GEMM, 512 threads. grid (12 slots, 2 nh, 340 mtiles):
// slot fastest => 24 consecutive blocks share one A tile -> A served from L2.
__global__ void __launch_bounds__(512) k_kvgemm(
    const __nv_bfloat16* __restrict__ Ahi, const __nv_bfloat16* __restrict__ Alo,
    const __nv_bfloat16* __restrict__ Whi, const __nv_bfloat16* __restrict__ Wlo,
    const float* __restrict__ bkv, float* __restrict__ Cbuf)
{
    extern __shared__ char sm[];
    uint32_t sb = smem_u32(sm);
    int tid = threadIdx.x, lane = tid & 31, warp = tid >> 5;
    int slot = blockIdx.x, nh = blockIdx.y, mt = blockIdx.z;
    size_t arow0 = (size_t)mt * 128;
    const __nv_bfloat16* wh = Whi + (size_t)slot*65536 + (size_t)nh*128*256;
    const __nv_bfloat16* wl = Wlo + (size_t)slot*65536 + (size_t)nh*128*256;

    int wm = warp >> 2, wn = warp & 3;           // warp tile: 32m x 32n

    float acc[2][4][4];
#pragma unroll
    for (int mi = 0; mi < 2; mi++)
#pragma unroll
        for (int ni = 0; ni < 4; ni++)
#pragma unroll
            for (int k = 0; k < 4; k++) acc[mi][ni][k] = 0.f;

    auto prefetch = [&](int ck, int buf){
        uint32_t stage = sb + buf*65536;
#pragma unroll
        for (int it = 0; it < 2; it++){
            int i = tid + it*512;
            int row = i >> 3, g = i & 7;
            uint32_t so = stage + row*128 + (((g ^ (row & 7)) << 4));
            cp16(so,         Ahi + (arow0 + row)*256 + ck*64 + g*8);
            cp16(so + 16384, Alo + (arow0 + row)*256 + ck*64 + g*8);
            cp16(so + 32768, wh + row*256 + ck*64 + g*8);
            cp16(so + 49152, wl + row*256 + ck*64 + g*8);
        }
        cp_commit();
    };

    prefetch(0, 0);

    for (int ck = 0; ck < 4; ck++){
        int buf = ck & 1;
        if (ck + 1 < 4){ prefetch(ck + 1, (ck + 1) & 1); cp_wait<1>(); }
        else           { cp_wait<0>(); }
        __syncthreads();

        uint32_t stage = sb + buf*65536;
#pragma unroll
        for (int k16 = 0; k16 < 4; k16++){
            int msel = lane >> 3;
            int rsub = (msel & 1)*8 + (lane & 7);
            int gg   = k16*2 + (msel >> 1);
            uint32_t ah[2][4], al[2][4];
#pragma unroll
            for (int mi = 0; mi < 2; mi++){
                int r = wm*32 + mi*16 + rsub;
                uint32_t ad = stage + r*128 + (((gg ^ (r & 7)) << 4));
                ldsm4(ah[mi], ad);
                ldsm4(al[mi], ad + 16384);
            }
            uint32_t bh[2][4], bl[2][4];
#pragma unroll
            for (int nj = 0; nj < 2; nj++){
                int r = wn*32 + nj*16 + rsub;
                uint32_t ad = stage + 32768 + r*128 + (((gg ^ (r & 7)) << 4));
                ldsm4(bh[nj], ad);
                ldsm4(bl[nj], ad + 16384);
            }
#pragma unroll
            for (int mi = 0; mi < 2; mi++)
#pragma unroll
                for (int ni = 0; ni < 4; ni++){
                    int nj = ni >> 1, sel = ni & 1;
                    mma16816(acc[mi][ni], ah[mi], bh[nj][sel], bh[nj][2+sel]);
                    mma16816(acc[mi][ni], ah[mi], bl[nj][sel], bl[nj][2+sel]);
                    mma16816(acc[mi][ni], al[mi], bh[nj][sel], bh[nj][2+sel]);
                }
        }
        __syncthreads();
    }

    float* st = reinterpret_cast<float*>(sm);
#pragma unroll
    for (int mi = 0; mi < 2; mi++)
#pragma unroll
        for (int ni = 0; ni < 4; ni++){
            int r0 = wm*32 + mi*16 + (lane >> 2);
            int c0 = wn*32 + ni*8 + (lane & 3)*2;
            *reinterpret_cast<float2*>(st + r0*132 + c0)       = make_float2(acc[mi][ni][0], acc[mi][ni][1]);
            *reinterpret_cast<float2*>(st + (r0 + 8)*132 + c0) = make_float2(acc[mi][ni][2], acc[mi][ni][3]);
        }
    __syncthreads();
    const float4* bp4 = reinterpret_cast<const float4*>(bkv + slot*256 + nh*128);
    float* dst = Cbuf + (size_t)slot*KVSZ + arow0*256 + nh*128;
#pragma unroll
    for (int it = 0; it < 8; it++){
        int i = tid + it*512;
        int row = i >> 5, q = i & 31;
        float4 v = *reinterpret_cast<float4*>(st + row*132 + q*4);
        float4 bb = bp4[q];
        v.x += bb.x; v.y += bb.y; v.z += bb.z; v.w += bb.w;
        *reinterpret_cast<float4*>(dst + (size_t)row*256 + q*4) = v;
    }
}

// ---- mma.sync small GEMM: C[.,N] = A(hi/lo)[.,256] @ Wt(hi/lo)^T (+bias) ----
__global__ void __launch_bounds__(256) k_qgemm(
    const __nv_bfloat16* __restrict__ Ah, const __nv_bfloat16* __restrict__ Al,
    const __nv_bfloat16* __restrict__ Wh, const __nv_bfloat16* __restrict__ Wl,
    const float* __restrict__ bias, float* __restrict__ C, int ldc)
{
    extern __shared__ char sm[];
    uint32_t sb = smem_u32(sm);
    int tid = threadIdx.x, lane = tid & 31, warp = tid >> 5;
    int mt = blockIdx.x, nt = blockIdx.y;
    size_t arow0 = (size_t)mt * 128;
    const __nv_bfloat16* wh = Wh + (size_t)nt*128*256;
    const __nv_bfloat16* wl = Wl + (size_t)nt*128*256;

    int wm = warp >> 1, wn = warp & 1;

    float acc[2][8][4];
#pragma unroll
    for (int mi = 0; mi < 2; mi++)
#pragma unroll
        for (int ni = 0; ni < 8; ni++)
#pragma unroll
            for (int k = 0; k < 4; k++) acc[mi][ni][k] = 0.f;

    auto prefetch = [&](int ck, int buf){
        uint32_t stage = sb + buf*65536;
#pragma unroll
        for (int it = 0; it < 4; it++){
            int i = tid + it*256;
            int row = i >> 3, g = i & 7;
            uint32_t so = stage + row*128 + (((g ^ (row & 7)) << 4));
            cp16(so,         Ah + (arow0 + row)*256 + ck*64 + g*8);
            cp16(so + 16384, Al + (arow0 + row)*256 + ck*64 + g*8);
            cp16(so + 32768, wh + row*256 + ck*64 + g*8);
            cp16(so + 49152, wl + row*256 + ck*64 + g*8);
        }
        cp_commit();
    };

    prefetch(0, 0);

    for (int ck = 0; ck < 4; ck++){
        int buf = ck & 1;
        if (ck + 1 < 4){ prefetch(ck + 1, (ck + 1) & 1); cp_wait<1>(); }
        else           { cp_wait<0>(); }
        __syncthreads();

        uint32_t stage = sb + buf*65536;
#pragma unroll
        for (int k16 = 0; k16 < 4; k16++){
            int msel = lane >> 3;
            int rsub = (msel & 1)*8 + (lane & 7);
            int gg   = k16*2 + (msel >> 1);
            uint32_t ah[2][4], al[2][4];
#pragma unroll
            for (int mi = 0; mi < 2; mi++){
                int r = wm*32 + mi*16 + rsub;
                uint32_t ad = stage + r*128 + (((gg ^ (r & 7)) << 4));
                ldsm4(ah[mi], ad);
                ldsm4(al[mi], ad + 16384);
            }
            uint32_t bh[4][4], bl[4][4];
#pragma unroll
            for (int nj = 0; nj < 4; nj++){
                int r = wn*64 + nj*16 + rsub;
                uint32_t ad = stage + 32768 + r*128 + (((gg ^ (r & 7)) << 4));
                ldsm4(bh[nj], ad);
                ldsm4(bl[nj], ad + 16384);
            }
#pragma unroll
            for (int mi = 0; mi < 2; mi++)
#pragma unroll
                for (int ni = 0; ni < 8; ni++){
                    int nj = ni >> 1, sel = ni & 1;
                    mma16816(acc[mi][ni], ah[mi], bh[nj][sel], bh[nj][2+sel]);
                    mma16816(acc[mi][ni], ah[mi], bl[nj][sel], bl[nj][2+sel]);
                    mma16816(acc[mi][ni], al[mi], bh[nj][sel], bh[nj][2+sel]);
                }
        }
        __syncthreads();
    }

    int n0 = nt*128;
#pragma unroll
    for (int mi = 0; mi < 2; mi++){
#pragma unroll
        for (int ni = 0; ni < 8; ni++){
            int row = (int)arow0 + wm*32 + mi*16 + (lane >> 2);
            int col = n0 + wn*64 + ni*8 + (lane & 3)*2;
            float bx = bias ? bias[col]     : 0.f;
            float by = bias ? bias[col + 1] : 0.f;
            float2 v0 = make_float2(acc[mi][ni][0] + bx, acc[mi][ni][1] + by);
            float2 v1 = make_float2(acc[mi][ni][2] + bx, acc[mi][ni][3] + by);
            *reinterpret_cast<float2*>(C + (size_t)row*ldc + col) = v0;
            *reinterpret_cast<float2*>(C + (size_t)(row + 8)*ldc + col) = v1;
        }
    }
}

// ---- LN rows of qsa -> bf16 hi/lo ----
__global__ void __launch_bounds__(256) k_lnsplit(const float* __restrict__ in,
    __nv_bfloat16* __restrict__ xh, __nv_bfloat16* __restrict__ xl)
{
    __shared__ float sh[32];
    int row = blockIdx.x, c = threadIdx.x;
    float x = in[(size_t)row*256 + c];
    float m = blockSum(x, sh) * (1.f/256.f);
    float d = x - m;
    float var = blockSum(d*d, sh) * (1.f/256.f);
    float v = d * rsqrtf(var + 1e-5f);
    hilo(v, &xh[(size_t)row*256 + c], &xl[(size_t)row*256 + c]);
}

// ---------------- self-attention over 100 keys, per (h, b, l) ----------------
__global__ void __launch_bounds__(128) k_sa(const float* __restrict__ qkv,
                                            __nv_bfloat16* __restrict__ oh,
                                            __nv_bfloat16* __restrict__ ol){
    __shared__ __align__(16) float sK[100][32];
    __shared__ __align__(16) float sV[100][32];
    int h = blockIdx.x, b = blockIdx.y, l = blockIdx.z;
    int lb = l*4 + b;
    const float* qb = qkv + (size_t)lb*100*768;
    for (int idx = threadIdx.x; idx < 1600; idx += 128){
        int arr = (idx >= 800);
        int rem = arr ? idx - 800 : idx;
        int row = rem >> 3, qd = rem & 7;
        float4 v = *reinterpret_cast<const float4*>(
            qb + (size_t)row*768 + 256 + arr*256 + h*32 + qd*4);
        float* dstp = arr ? &sV[row][qd*4] : &sK[row][qd*4];
        *reinterpret_cast<float4*>(dstp) = v;
    }
    __syncthreads();
    int i = threadIdx.x;
    if (i < 100){
        float Q[32];
        const float4* qp4 = reinterpret_cast<const float4*>(qb + (size_t)i*768 + h*32);
#pragma unroll
        for (int qd = 0; qd < 8; qd++){
            float4 v = qp4[qd];
            Q[qd*4+0] = v.x; Q[qd*4+1] = v.y; Q[qd*4+2] = v.z; Q[qd*4+3] = v.w;
        }
        float m = -1e30f, s = 0.f, acc[32];
#pragma unroll
        for (int c = 0; c < 32; c++) acc[c] = 0.f;
        for (int j = 0; j < 100; j++){
            const float4* k4 = reinterpret_cast<const float4*>(sK[j]);
            float d = 0.f;
#pragma unroll
            for (int qd = 0; qd < 8; qd++){
                float4 kv = k4[qd];
                d = fmaf(Q[qd*4+0], kv.x, d); d = fmaf(Q[qd*4+1], kv.y, d);
                d = fmaf(Q[qd*4+2], kv.z, d); d = fmaf(Q[qd*4+3], kv.w, d);
            }
            d *= 0.17677669529663687f;
            const float4* v4 = reinterpret_cast<const float4*>(sV[j]);
            if (d > m){
                float f = __expf(m - d);
                m = d; s = fmaf(s, f, 1.f);
#pragma unroll
                for (int qd = 0; qd < 8; qd++){
                    float4 vv = v4[qd];
                    acc[qd*4+0] = fmaf(acc[qd*4+0], f, vv.x);
                    acc[qd*4+1] = fmaf(acc[qd*4+1], f, vv.y);
                    acc[qd*4+2] = fmaf(acc[qd*4+2], f, vv.z);
                    acc[qd*4+3] = fmaf(acc[qd*4+3], f, vv.w);
                }
            } else {
                float p = __expf(d - m);
                s += p;
#pragma unroll
                for (int qd = 0; qd < 8; qd++){
                    float4 vv = v4[qd];
                    acc[qd*4+0] = fmaf(p, vv.x, acc[qd*4+0]);
                    acc[qd*4+1] = fmaf(p, vv.y, acc[qd*4+1]);
                    acc[qd*4+2] = fmaf(p, vv.z, acc[qd*4+2]);
                    acc[qd*4+3] = fmaf(p, vv.w, acc[qd*4+3]);
                }
            }
        }
        float inv = 1.f / s;
        size_t ob = (size_t)(lb*100 + i)*256 + h*32;
#pragma unroll
        for (int c = 0; c < 32; c++)
            hilo(acc[c]*inv, &oh[ob + c], &ol[ob + c]);
    }
}

// ---- cross-attention flash partials: 256 threads, lane pair splits 32 dims ----
__global__ void __launch_bounds__(256) k_cross(
    const float* __restrict__ qn, const float* __restrict__ Kg,
    const float* __restrict__ Vg, float* __restrict__ pm,
    float* __restrict__ ps, float* __restrict__ pacc)
{
    __shared__ __align__(16) float sKV[2][2][64][32];
    int ss = blockIdx.x, h = blockIdx.y, vb = blockIdx.z;
    int v = vb >> 2, b = vb & 3;
    int l = c_sl[ss];
    int Nl = c_N[l];
    int ck = c_ck[ss];
    int kbeg = c_sk[ss]*ck;
    int lb = l*4 + b;
    size_t kvbase = ((size_t)v*TOKV + c_off[l] + (size_t)b*Nl)*256 + h*32;
    const float* Kp = Kg + kvbase;
    const float* Vp = Vg + kvbase;
    int tid = threadIdx.x;
    int warp = tid >> 5, lane = tid & 31;
    int qi = warp*16 + (lane & 15);     // query 0..127
    int half = lane >> 4;               // dim half
    bool active = qi < 100;
    uint32_t sbase = smem_u32(&sKV[0][0][0][0]);

    auto prefetch = [&](int kc, int buf){
        uint32_t stage = sbase + buf*16384;
#pragma unroll
        for (int it = 0; it < 4; it++){
            int idx = tid + it*256;
            int a = idx >> 9, rem = idx & 511;
            int row = rem >> 3, qd = rem & 7;
            const float* src = (a ? Vp : Kp) + (size_t)(kc + row)*256 + qd*4;
            cp16(stage + a*8192 + row*128 + qd*16, src);
        }
        cp_commit();
    };

    float Q[16];
#pragma unroll
    for (int c = 0; c < 16; c++) Q[c] = 0.f;
    if (active){
        const float4* qp4 = reinterpret_cast<const float4*>(
            qn + (size_t)(lb*100 + qi)*256 + h*32 + half*16);
#pragma unroll
        for (int qd = 0; qd < 4; qd++){
            float4 vq = qp4[qd];
            Q[qd*4+0] = vq.x; Q[qd*4+1] = vq.y; Q[qd*4+2] = vq.z; Q[qd*4+3] = vq.w;
        }
    }
    float m = -1e30f, s = 0.f, acc[16];
#pragma unroll
    for (int c = 0; c < 16; c++) acc[c] = 0.f;

    int nchunks = ck >> 6;
    prefetch(kbeg, 0);
    for (int cki = 0; cki < nchunks; cki++){
        int buf = cki & 1;
        if (cki + 1 < nchunks){ prefetch(kbeg + (cki+1)*64, buf ^ 1); cp_wait<1>(); }
        else                  { cp_wait<0>(); }
        __syncthreads();
        for (int j = 0; j < 64; j++){
            const float4* k4 = reinterpret_cast<const float4*>(&sKV[buf][0][j][half*16]);
            float d = 0.f;
#pragma unroll
            for (int qd = 0; qd < 4; qd++){
                float4 kv = k4[qd];
                d = fmaf(Q[qd*4+0], kv.x, d); d = fmaf(Q[qd*4+1], kv.y, d);
                d = fmaf(Q[qd*4+2], kv.z, d); d = fmaf(Q[qd*4+3], kv.w, d);
            }
            d += __shfl_xor_sync(0xffffffffu, d, 16);
            d *= 0.17677669529663687f;
            const float4* v4 = reinterpret_cast<const float4*>(&sKV[buf][1][j][half*16]);
            if (d > m){
                float f = __expf(m - d);
                m = d; s = fmaf(s, f, 1.f);
#pragma unroll
                for (int qd = 0; qd < 4; qd++){
                    float4 vv = v4[qd];
                    acc[qd*4+0] = fmaf(acc[qd*4+0], f, vv.x);
                    acc[qd*4+1] = fmaf(acc[qd*4+1], f, vv.y);
                    acc[qd*4+2] = fmaf(acc[qd*4+2], f, vv.z);
                    acc[qd*4+3] = fmaf(acc[qd*4+3], f, vv.w);
                }
            } else {
                float p = __expf(d - m);
                s += p;
#pragma unroll
                for (int qd = 0; qd < 4; qd++){
                    float4 vv = v4[qd];
                    acc[qd*4+0] = fmaf(p, vv.x, acc[qd*4+0]);
                    acc[qd*4+1] = fmaf(p, vv.y, acc[qd*4+1]);
                    acc[qd*4+2] = fmaf(p, vv.z, acc[qd*4+2]);
                    acc[qd*4+3] = fmaf(p, vv.w, acc[qd*4+3]);
                }
            }
        }
        __syncthreads();
    }
    if (active){
        int slot = (vb*8 + h)*22 + ss;
        if (half == 0){
            pm[slot*100 + qi] = m;
            ps[slot*100 + qi] = s;
        }
        float* pa = pacc + (size_t)(slot*100 + qi)*32 + half*16;
#pragma unroll
        for (int c = 0; c < 16; c++) pa[c] = acc[c];
    }
}

__global__ void __launch_bounds__(128) k_combine(
    const float* __restrict__ pm, const float* __restrict__ ps,
    const float* __restrict__ pacc,
    __nv_bfloat16* __restrict__ och, __nv_bfloat16* __restrict__ ocl)
{
    int l = blockIdx.x, h = blockIdx.y, vb = blockIdx.z;
    int i = threadIdx.x;
    if (i >= 100) return;
    int S = c_S[l], s0 = c_s0[l];
    int base = (vb*8 + h)*22 + s0;
    float M = -1e30f;
    for (int k = 0; k < S; k++) M = fmaxf(M, pm[(base + k)*100 + i]);
    float Ss = 0.f, acc[32];
#pragma unroll
    for (int c = 0; c < 32; c++) acc[c] = 0.f;
    for (int k = 0; k < S; k++){
        int slot = base + k;
        float f = __expf(pm[slot*100 + i] - M);
        Ss = fmaf(ps[slot*100 + i], f, Ss);
        const float* pa = pacc + (size_t)(slot*100 + i)*32;
#pragma unroll
        for (int c = 0; c < 32; c++) acc[c] = fmaf(pa[c], f, acc[c]);
    }
    float inv = 1.f / Ss;
    int v = vb >> 2, b = vb & 3;
    int lb = l*4 + b;
    size_t ob = (size_t)(v*1600 + lb*100 + i)*256 + h*32;
#pragma unroll
    for (int c = 0; c < 32; c++)
        hilo(acc[c]*inv, &och[ob + c], &ocl[ob + c]);
}

// ---- matching score + both softmaxes, one block per lb ----
__global__ void __launch_bounds__(256) k_matchsm(const float* __restrict__ q12,
                                                 float* __restrict__ wr,
                                                 float* __restrict__ wc){
    extern __shared__ float buf[];          // >= 10100 floats
    float* sA = buf;                        // [100][33]
    float* sB = buf + 3300;                 // [100][33]
    int lb = blockIdx.x;
    int tid = threadIdx.x;
    int tx = tid & 15, ty = tid >> 4;
    const float* q1 = q12 + (size_t)lb*25600;
    const float* q2 = q12 + 409600 + (size_t)lb*25600;
    float acc[7][7];
#pragma unroll
    for (int a = 0; a < 7; a++)
#pragma unroll
        for (int bq = 0; bq < 7; bq++) acc[a][bq] = 0.f;
    for (int k0 = 0; k0 < 256; k0 += 32){
        __syncthreads();
        for (int idx = tid; idx < 3200; idx += 256){
            int r = idx >> 5, kk = idx & 31;
            sA[r*33 + kk] = q1[(size_t)r*256 + k0 + kk];
            sB[r*33 + kk] = q2[(size_t)r*256 + k0 + kk];
        }
        __syncthreads();
        for (int kk = 0; kk < 32; kk++){
            float a[7], b[7];
#pragma unroll
            for (int ii = 0; ii < 7; ii++){
                int i = ty + 16*ii;
                a[ii] = (i < 100) ? sA[i*33 + kk] : 0.f;
            }
#pragma unroll
            for (int jj = 0; jj < 7; jj++){
                int j = tx + 16*jj;
                b[jj] = (j < 100) ? sB[j*33 + kk] : 0.f;
            }
#pragma unroll
            for (int ii = 0; ii < 7; ii++)
#pragma unroll
                for (int jj = 0; jj < 7; jj++) acc[ii][jj] = fmaf(a[ii], b[jj], acc[ii][jj]);
        }
    }
    __syncthreads();                        // reuse buf as ms[100][101]
#pragma unroll
    for (int ii = 0; ii < 7; ii++){
        int i = ty + 16*ii;
        if (i < 100){
#pragma unroll
            for (int jj = 0; jj < 7; jj++){
                int j = tx + 16*jj;
                if (j < 100) buf[i*101 + j] = acc[ii][jj];
            }
        }
    }
    __syncthreads();
    int w = tid >> 5, lane = tid & 31;
    for (int r = w; r < 100; r += 8){
        float v0 = buf[r*101 + lane];
        float v1 = buf[r*101 + 32 + lane];
        float v2 = buf[r*101 + 64 + lane];
        float v3 = (lane < 4) ? buf[r*101 + 96 + lane] : -1e30f;
        float M = warpMax(fmaxf(fmaxf(v0, v1), fmaxf(v2, v3)));
        float p0 = __expf(v0 - M), p1 = __expf(v1 - M), p2 = __expf(v2 - M);
        float p3 = (lane < 4) ? __expf(v3 - M) : 0.f;
        float S = warpSum(p0 + p1 + p2 + p3);
        float inv = 1.f / S;
        float* o = wr + (size_t)lb*10000 + r*100;
        o[lane] = p0*inv; o[32 + lane] = p1*inv; o[64 + lane] = p2*inv;
        if (lane < 4) o[96 + lane] = p3*inv;
    }
    for (int cc = w; cc < 100; cc += 8){
        float v0 = buf[lane*101 + cc];
        float v1 = buf[(32 + lane)*101 + cc];
        float v2 = buf[(64 + lane)*101 + cc];
        float v3 = (lane < 4) ? buf[(96 + lane)*101 + cc] : -1e30f;
        float M = warpMax(fmaxf(fmaxf(v0, v1), fmaxf(v2, v3)));
        float p0 = __expf(v0 - M), p1 = __expf(v1 - M), p2 = __expf(v2 - M);
        float p3 = (lane < 4) ? __expf(v3 - M) : 0.f;
        float S = warpSum(p0 + p1 + p2 + p3);
        float inv = 1.f / S;
        float* o = wc + (size_t)lb*10000 + cc;
        o[lane*100] = p0*inv; o[(32 + lane)*100] = p1*inv; o[(64 + lane)*100] = p2*inv;
        if (lane < 4) o[(96 + lane)*100] = p3*inv;
    }
}

// -------- fuse (4 queries/block): t = qsa+q1+q2+Wr@q2+Wc^T@q1; softmax over c ----
__global__ void __launch_bounds__(256) k_fuse(
    const float* __restrict__ qsa, const float* __restrict__ q12,
    const float* __restrict__ wr, const float* __restrict__ wc,
    __nv_bfloat16* __restrict__ qh, __nv_bfloat16* __restrict__ ql,
    float* __restrict__ outp)
{
    __shared__ float swr[4][100];
    __shared__ float swc[4][100];
    __shared__ float sh[32];
    int i0 = blockIdx.x * 4, lb = blockIdx.y, c = threadIdx.x;
    const float* q1 = q12 + (size_t)lb*25600;
    const float* q2 = q12 + 409600 + (size_t)lb*25600;
    for (int idx = c; idx < 400; idx += 256){
        int ii = idx / 100, j = idx % 100;
        swr[ii][j] = wr[(size_t)lb*10000 + (i0+ii)*100 + j];
        swc[ii][j] = wc[(size_t)lb*10000 + j*100 + (i0+ii)];
    }
    __syncthreads();
    float acc[4];
#pragma unroll
    for (int ii = 0; ii < 4; ii++)
        acc[ii] = qsa[(size_t)(lb*100 + i0+ii)*256 + c]
                + q1[(size_t)(i0+ii)*256 + c] + q2[(size_t)(i0+ii)*256 + c];
    for (int j = 0; j < 100; j++){
        float q1v = q1[(size_t)j*256 + c];
        float q2v = q2[(size_t)j*256 + c];
#pragma unroll
        for (int ii = 0; ii < 4; ii++){
            acc[ii] = fmaf(swr[ii][j], q2v, acc[ii]);
            acc[ii] = fmaf(swc[ii][j], q1v, acc[ii]);
        }
    }
#pragma unroll
    for (int ii = 0; ii < 4; ii++){
        float M = blockMax(acc[ii], sh);
        float e = __expf(acc[ii] - M);
        float S = blockSum(e, sh);
        float val = e / S;
        size_t off = (size_t)(lb*100 + i0+ii)*256 + c;
        if (outp) outp[off] = val;
        else      hilo(val, &qh[off], &ql[off]);
    }
}

// ---------------- host ----------------
extern "C" void kernel_launch(void* const* d_in, const int* in_sizes, int n_in,
                              void* d_out, int out_size)
{
    float* arena;   cudaGetSymbolAddress((void**)&arena, g_buf);
    float* kvbuf;   cudaGetSymbolAddress((void**)&kvbuf, g_kv);
    __nv_bfloat16 *ahi, *alo, *whi, *wlo;
    cudaGetSymbolAddress((void**)&ahi, g_ahi);
    cudaGetSymbolAddress((void**)&alo, g_alo);
    cudaGetSymbolAddress((void**)&whi, g_whi);
    cudaGetSymbolAddress((void**)&wlo, g_wlo);
    float* bkv;     cudaGetSymbolAddress((void**)&bkv, g_bkv);
    __nv_bfloat16 *qh, *ql, *oh, *ol, *xh, *xl, *och, *ocl;
    cudaGetSymbolAddress((void**)&qh, g_qh);   cudaGetSymbolAddress((void**)&ql, g_ql);
    cudaGetSymbolAddress((void**)&oh, g_oh);   cudaGetSymbolAddress((void**)&ol, g_ol);
    cudaGetSymbolAddress((void**)&xh, g_xh);   cudaGetSymbolAddress((void**)&xl, g_xl);
    cudaGetSymbolAddress((void**)&och, g_och); cudaGetSymbolAddress((void**)&ocl, g_ocl);
    __nv_bfloat16 *wqkvh, *wqkvl, *wswh, *wswl, *wqh2, *wql2, *wph, *wpl;
    cudaGetSymbolAddress((void**)&wqkvh, g_wqkvh); cudaGetSymbolAddress((void**)&wqkvl, g_wqkvl);
    cudaGetSymbolAddress((void**)&wswh, g_wswh);   cudaGetSymbolAddress((void**)&wswl, g_wswl);
    cudaGetSymbolAddress((void**)&wqh2, g_wqh);    cudaGetSymbolAddress((void**)&wql2, g_wql);
    cudaGetSymbolAddress((void**)&wph, g_wph);     cudaGetSymbolAddress((void**)&wpl, g_wpl);
    float *bsw, *bwq, *bwp;
    cudaGetSymbolAddress((void**)&bsw, g_bsw);
    cudaGetSymbolAddress((void**)&bwq, g_bwq);
    cudaGetSymbolAddress((void**)&bwp, g_bwp);

    float* qkv  = arena;                 // 1,277,952 (1664*768)
    float* qsa  = arena + 1277952;       // 425,984
    float* qn   = arena + 1703936;       // 425,984
    float* q12  = arena + 2129920;       // 819,200
    float* wr   = arena + 2949120;       // 160,000
    float* wc   = arena + 3109120;       // 160,000
    float* pm   = arena + 3269120;       // 140,800
    float* ps   = arena + 3409920;       // 140,800
    float* pacc = arena + 3550720;       // 4,505,600

    FeatPtrs fp;
    for (int i = 0; i < 8; i++) fp.p[i] = (const float*)d_in[i];
    const float* qe   = (const float*)d_in[8];
    const float* ng   = (const float*)d_in[9];
    const float* nb   = (const float*)d_in[10];
    const float* wq   = (const float*)d_in[11];
    const float* wk   = (const float*)d_in[12];
    const float* wv   = (const float*)d_in[13];
    const float* wp   = (const float*)d_in[14];
    const float* bp   = (const float*)d_in[15];
    const float* wqkv = (const float*)d_in[16];
    const float* swp  = (const float*)d_in[17];
    const float* sbp  = (const float*)d_in[18];

    cudaFuncSetAttribute(k_kvgemm, cudaFuncAttributeMaxDynamicSharedMemorySize, 131072);
    cudaFuncSetAttribute(k_qgemm,  cudaFuncAttributeMaxDynamicSharedMemorySize, 131072);

    k_init_q<<<1600, 256>>>(qe, qh, ql);
    k_tok_ln<<<dim3(680, 2), 256>>>(fp, ahi, alo);
    k_prep_w<<<12, 256>>>(wk, wv, ng, nb, whi, wlo, bkv);
    k_kvgemm<<<dim3(12, 2, 340), 512, 131072>>>(ahi, alo, whi, wlo, bkv, kvbuf); // profiled
    k_prep_wt<<<dim3(3, 6), 256>>>(wqkv, nullptr, nullptr, nullptr, wqkvh, wqkvl, nullptr, 768);
    k_prep_wt<<<dim3(1, 6), 256>>>(swp, nullptr, nullptr, sbp, wswh, wswl, bsw, 256);
    k_prep_wt<<<dim3(1, 6), 256>>>(wq, ng, nb, nullptr, wqh2, wql2, bwq, 256);
    k_prep_wt<<<dim3(1, 6), 256>>>(wp, nullptr, nullptr, bp, wph, wpl, bwp, 256);

    for (int d = 0; d < 6; d++){
        k_qgemm<<<dim3(13, 6), 256, 131072>>>(qh, ql,
            wqkvh + (size_t)d*768*256, wqkvl + (size_t)d*768*256,
            nullptr, qkv, 768);
        k_sa<<<dim3(8, 4, 4), 128>>>(qkv, oh, ol);
        k_qgemm<<<dim3(13, 2), 256, 131072>>>(oh, ol,
            wswh + (size_t)d*65536, wswl + (size_t)d*65536,
            bsw + d*256, qsa, 256);
        k_lnsplit<<<1600, 256>>>(qsa, xh, xl);
        k_qgemm<<<dim3(13, 2), 256, 131072>>>(xh, xl,
            wqh2 + (size_t)d*65536, wql2 + (size_t)d*65536,
            bwq + d*256, qn, 256);
        k_cross<<<dim3(22, 8, 8), 256>>>(qn, kvbuf + (size_t)(2*d)*KVSZ,
                                         kvbuf + (size_t)(2*d+1)*KVSZ, pm, ps, pacc);
        k_combine<<<dim3(4, 8, 8), 128>>>(pm, ps, pacc, och, ocl);
        k_qgemm<<<dim3(25, 2), 256, 131072>>>(och, ocl,
            wph + (size_t)d*65536, wpl + (size_t)d*65536,
            bwp + d*256, q12, 256);
        k_matchsm<<<16, 256, 10100*sizeof(float)>>>(q12, wr, wc);
        k_fuse<<<dim3(25, 16), 256>>>(qsa, q12, wr, wc, qh, ql,
                                      (d == 5) ? (float*)d_out : nullptr);
    }
}

// round 14
// speedup vs baseline: 1.3327x; 1.0054x over previous
#include <cuda_runtime.h>
#include <cuda_bf16.h>
#include <cstdint>
#include <math.h>

#define TOKV 21760            // per-view feature tokens: 4*(4096+1024+256+64)
#define AROWS 43520           // 2 views
#define KVSZ  11141120        // 43520*256
#define MPAD  1664            // 1600 padded to 13*128

__constant__ int c_N[4]   = {4096, 1024, 256, 64};
__constant__ int c_off[4] = {0, 16384, 20480, 21504};
// 22 cross-attn split slots (256-key chunks; level 3 has 64)
__constant__ int c_sl[22] = {0,0,0,0,0,0,0,0,0,0,0,0,0,0,0,0, 1,1,1,1, 2, 3};
__constant__ int c_sk[22] = {0,1,2,3,4,5,6,7,8,9,10,11,12,13,14,15, 0,1,2,3, 0, 0};
__constant__ int c_ck[22] = {256,256,256,256,256,256,256,256,256,256,256,256,256,256,256,256,
                             256,256,256,256, 256, 64};
__constant__ int c_S[4]  = {16,4,1,1};
__constant__ int c_s0[4] = {0,16,20,21};

// ---- device scratch (allocations forbidden) ----
__device__ float g_kv[12*KVSZ];
__device__ __nv_bfloat16 g_ahi[AROWS*256];
__device__ __nv_bfloat16 g_alo[AROWS*256];
__device__ __nv_bfloat16 g_whi[12*256*256];
__device__ __nv_bfloat16 g_wlo[12*256*256];
__device__ float g_bkv[12*256];
__device__ __nv_bfloat16 g_qh[MPAD*256],  g_ql[MPAD*256];
__device__ __nv_bfloat16 g_oh[MPAD*256],  g_ol[MPAD*256];
__device__ __nv_bfloat16 g_xh[MPAD*256],  g_xl[MPAD*256];
__device__ __nv_bfloat16 g_och[3200*256], g_ocl[3200*256];
__device__ __nv_bfloat16 g_wqkvh[6*768*256], g_wqkvl[6*768*256];
__device__ __nv_bfloat16 g_wswh[6*256*256],  g_wswl[6*256*256];
__device__ __nv_bfloat16 g_wqh[6*256*256],   g_wql[6*256*256];
__device__ __nv_bfloat16 g_wph[6*256*256],   g_wpl[6*256*256];
__device__ float g_bsw[1536], g_bwq[1536], g_bwp[1536];
__device__ float g_buf[9000000];

struct FeatPtrs { const float* p[8]; };

// ---------------- PTX helpers ----------------
__device__ __forceinline__ uint32_t smem_u32(const void* p){
    uint32_t a;
    asm("{ .reg .u64 t; cvta.to.shared.u64 t, %1; cvt.u32.u64 %0, t; }" : "=r"(a) : "l"(p));
    return a;
}
__device__ __forceinline__ void cp16(uint32_t s, const void* g){
    asm volatile("cp.async.cg.shared.global [%0], [%1], 16;" :: "r"(s), "l"(g) : "memory");
}
__device__ __forceinline__ void cp_commit(){
    asm volatile("cp.async.commit_group;" ::: "memory");
}
template<int N>
__device__ __forceinline__ void cp_wait(){
    asm volatile("cp.async.wait_group %0;" :: "n"(N) : "memory");
}
__device__ __forceinline__ void ldsm4(uint32_t* r, uint32_t a){
    asm volatile("ldmatrix.sync.aligned.m8n8.x4.shared.b16 {%0,%1,%2,%3}, [%4];"
                 : "=r"(r[0]), "=r"(r[1]), "=r"(r[2]), "=r"(r[3]) : "r"(a));
}
__device__ __forceinline__ void mma16816(float* c, const uint32_t* a,
                                         uint32_t b0, uint32_t b1){
    asm volatile(
        "mma.sync.aligned.m16n8k16.row.col.f32.bf16.bf16.f32 "
        "{%0,%1,%2,%3}, {%4,%5,%6,%7}, {%8,%9}, {%0,%1,%2,%3};"
        : "+f"(c[0]), "+f"(c[1]), "+f"(c[2]), "+f"(c[3])
        : "r"(a[0]), "r"(a[1]), "r"(a[2]), "r"(a[3]), "r"(b0), "r"(b1));
}
__device__ __forceinline__ void hilo(float v, __nv_bfloat16* ph, __nv_bfloat16* pl){
    __nv_bfloat16 h = __float2bfloat16(v);
    *ph = h;
    *pl = __float2bfloat16(v - __bfloat162float(h));
}

// ---------------- reductions ----------------
__device__ __forceinline__ float warpSum(float v){
#pragma unroll
    for (int o = 16; o > 0; o >>= 1) v += __shfl_xor_sync(0xffffffffu, v, o);
    return v;
}
__device__ __forceinline__ float warpMax(float v){
#pragma unroll
    for (int o = 16; o > 0; o >>= 1) v = fmaxf(v, __shfl_xor_sync(0xffffffffu, v, o));
    return v;
}
__device__ __forceinline__ float blockSum(float v, float* sh){
    int lane = threadIdx.x & 31, w = threadIdx.x >> 5;
    int nw = blockDim.x >> 5;
    __syncthreads();
    v = warpSum(v);
    if (lane == 0) sh[w] = v;
    __syncthreads();
    if (w == 0){
        float r = (threadIdx.x < nw) ? sh[threadIdx.x] : 0.f;
        r = warpSum(r);
        if (lane == 0) sh[0] = r;
    }
    __syncthreads();
    return sh[0];
}
__device__ __forceinline__ float blockMax(float v, float* sh){
    int lane = threadIdx.x & 31, w = threadIdx.x >> 5;
    int nw = blockDim.x >> 5;
    __syncthreads();
    v = warpMax(v);
    if (lane == 0) sh[w] = v;
    __syncthreads();
    if (w == 0){
        float r = (threadIdx.x < nw) ? sh[threadIdx.x] : -1e30f;
        r = warpMax(r);
        if (lane == 0) sh[0] = r;
    }
    __syncthreads();
    return sh[0];
}

// ---- tokenize + LN normalization -> bf16 hi/lo ----
__global__ void __launch_bounds__(256) k_tok_ln(FeatPtrs fp,
    __nv_bfloat16* __restrict__ ahi, __nv_bfloat16* __restrict__ alo)
{
    __shared__ float s[256][33];
    __shared__ float ps[8][32], pq[8][32];
    __shared__ float mean[32], rinv[32];
    int r = blockIdx.x, v = blockIdx.y;
    int l = (r < 512) ? 0 : (r < 640) ? 1 : (r < 672) ? 2 : 3;
    int off32 = (l == 0) ? 0 : (l == 1) ? 512 : (l == 2) ? 640 : 672;
    int Nl = c_N[l];
    int idx = r - off32;
    int tpb = Nl >> 5;
    int b = idx / tpb, t0 = (idx % tpb) * 32;
    const float* f = fp.p[v*4 + l];
    int g = threadIdx.x >> 5, t = threadIdx.x & 31;
    for (int cc = g; cc < 256; cc += 8)
        s[cc][t] = f[((size_t)(b*256 + cc))*Nl + t0 + t];
    __syncthreads();
    float sx = 0.f, sq = 0.f;
#pragma unroll
    for (int k = 0; k < 32; k++){
        float x = s[g*32 + k][t];
        sx += x; sq = fmaf(x, x, sq);
    }
    ps[g][t] = sx; pq[g][t] = sq;
    __syncthreads();
    if (threadIdx.x < 32){
        float m = 0.f, qq = 0.f;
#pragma unroll
        for (int gg = 0; gg < 8; gg++){ m += ps[gg][threadIdx.x]; qq += pq[gg][threadIdx.x]; }
        m *= (1.f/256.f);
        float var = qq*(1.f/256.f) - m*m;
        mean[threadIdx.x] = m;
        rinv[threadIdx.x] = rsqrtf(var + 1e-5f);
    }
    __syncthreads();
    int c = threadIdx.x;
    size_t rowbase = (size_t)v*TOKV + c_off[l] + (size_t)b*Nl + t0;
    for (int tt = 0; tt < 32; tt++){
        float val = (s[c][tt] - mean[tt]) * rinv[tt];
        hilo(val, &ahi[(rowbase + tt)*256 + c], &alo[(rowbase + tt)*256 + c]);
    }
}

// ---- prep KV weights: Wt[n][k] = g[k]*W[k][n] bf16 hi/lo; bias'[n] = b@W ----
__global__ void __launch_bounds__(256) k_prep_w(
    const float* __restrict__ wk, const float* __restrict__ wv,
    const float* __restrict__ ng, const float* __restrict__ nb,
    __nv_bfloat16* __restrict__ whi, __nv_bfloat16* __restrict__ wlo,
    float* __restrict__ bkv)
{
    int s = blockIdx.x, n = threadIdx.x;
    int d = s >> 1;
    const float* W = ((s & 1) ? wv : wk) + (size_t)d*65536;
    const float* g = ng + d*256;
    const float* b = nb + d*256;
    float bias = 0.f;
    size_t obase = ((size_t)s*256 + n)*256;
    for (int k = 0; k < 256; k++){
        float w0 = W[k*256 + n];
        bias = fmaf(b[k], w0, bias);
        float w = g[k]*w0;
        hilo(w, &whi[obase + k], &wlo[obase + k]);
    }
    bkv[s*256 + n] = bias;
}

// ---- generic weight prep ----
__global__ void __launch_bounds__(256) k_prep_wt(
    const float* __restrict__ W, const float* __restrict__ g,
    const float* __restrict__ bf, const float* __restrict__ ab,
    __nv_bfloat16* __restrict__ wh, __nv_bfloat16* __restrict__ wl,
    float* __restrict__ bo, int N)
{
    int d = blockIdx.y;
    int n = blockIdx.x*256 + threadIdx.x;
    const float* Wd = W + (size_t)d*256*N;
    float bias = ab ? ab[(size_t)d*N + n] : 0.f;
    size_t ob = ((size_t)d*N + n)*256;
    for (int k = 0; k < 256; k++){
        float w0 = Wd[(size_t)k*N + n];
        if (bf) bias = fmaf(bf[d*256 + k], w0, bias);
        float w = g ? g[d*256 + k]*w0 : w0;
        hilo(w, &wh[ob + k], &wl[ob + k]);
    }
    if (bo) bo[(size_t)d*N + n] = bias;
}

__global__ void k_init_q(const float* __restrict__ qe,
                         __nv_bfloat16* __restrict__ qh,
                         __nv_bfloat16* __restrict__ ql){
    int row = blockIdx.x, c = threadIdx.x;
    float val = qe[(row % 100)*256 + c];
    hilo(val, &qh[(size_t)row*256 + c], &ql[(size_t)row*256 + c]);
}

// ---- mma.sync KV GEMM, 512 threads. grid (12 slots, 2 nh, 340 mtiles) ----
__global__ void __launch_bounds__(512) k_kvgemm(
    const __nv_bfloat16* __restrict__ Ahi, const __nv_bfloat16* __restrict__ Alo,
    const __nv_bfloat16* __restrict__ Whi, const __nv_bfloat16* __restrict__ Wlo,
    const float* __restrict__ bkv, float* __restrict__ Cbuf)
{
    extern __shared__ char sm[];
    uint32_t sb = smem_u32(sm);
    int tid = threadIdx.x, lane = tid & 31, warp = tid >> 5;
    int slot = blockIdx.x, nh = blockIdx.y, mt = blockIdx.z;
    size_t arow0 = (size_t)mt * 128;
    const __nv_bfloat16* wh = Whi + (size_t)slot*65536 + (size_t)nh*128*256;
    const __nv_bfloat16* wl = Wlo + (size_t)slot*65536 + (size_t)nh*128*256;

    int wm = warp >> 2, wn = warp & 3;           // warp tile: 32m x 32n

    float acc[2][4][4];
#pragma unroll
    for (int mi = 0; mi < 2; mi++)
#pragma unroll
        for (int ni = 0; ni < 4; ni++)
#pragma unroll
            for (int k = 0; k < 4; k++) acc[mi][ni][k] = 0.f;

    auto prefetch = [&](int ck, int buf){
        uint32_t stage = sb + buf*65536;
#pragma unroll
        for (int it = 0; it < 2; it++){
            int i = tid + it*512;
            int row = i >> 3, g = i & 7;
            uint32_t so = stage + row*128 + (((g ^ (row & 7)) << 4));
            cp16(so,         Ahi + (arow0 + row)*256 + ck*64 + g*8);
            cp16(so + 16384, Alo + (arow0 + row)*256 + ck*64 + g*8);
            cp16(so + 32768, wh + row*256 + ck*64 + g*8);
            cp16(so + 49152, wl + row*256 + ck*64 + g*8);
        }
        cp_commit();
    };

    prefetch(0, 0);

    for (int ck = 0; ck < 4; ck++){
        int buf = ck & 1;
        if (ck + 1 < 4){ prefetch(ck + 1, (ck + 1) & 1); cp_wait<1>(); }
        else           { cp_wait<0>(); }
        __syncthreads();

        uint32_t stage = sb + buf*65536;
#pragma unroll
        for (int k16 = 0; k16 < 4; k16++){
            int msel = lane >> 3;
            int rsub = (msel & 1)*8 + (lane & 7);
            int gg   = k16*2 + (msel >> 1);
            uint32_t ah[2][4], al[2][4];
#pragma unroll
            for (int mi = 0; mi < 2; mi++){
                int r = wm*32 + mi*16 + rsub;
                uint32_t ad = stage + r*128 + (((gg ^ (r & 7)) << 4));
                ldsm4(ah[mi], ad);
                ldsm4(al[mi], ad + 16384);
            }
            uint32_t bh[2][4], bl[2][4];
#pragma unroll
            for (int nj = 0; nj < 2; nj++){
                int r = wn*32 + nj*16 + rsub;
                uint32_t ad = stage + 32768 + r*128 + (((gg ^ (r & 7)) << 4));
                ldsm4(bh[nj], ad);
                ldsm4(bl[nj], ad + 16384);
            }
#pragma unroll
            for (int mi = 0; mi < 2; mi++)
#pragma unroll
                for (int ni = 0; ni < 4; ni++){
                    int nj = ni >> 1, sel = ni & 1;
                    mma16816(acc[mi][ni], ah[mi], bh[nj][sel], bh[nj][2+sel]);
                    mma16816(acc[mi][ni], ah[mi], bl[nj][sel], bl[nj][2+sel]);
                    mma16816(acc[mi][ni], al[mi], bh[nj][sel], bh[nj][2+sel]);
                }
        }
        __syncthreads();
    }

    float* st = reinterpret_cast<float*>(sm);
#pragma unroll
    for (int mi = 0; mi < 2; mi++)
#pragma unroll
        for (int ni = 0; ni < 4; ni++){
            int r0 = wm*32 + mi*16 + (lane >> 2);
            int c0 = wn*32 + ni*8 + (lane & 3)*2;
            *reinterpret_cast<float2*>(st + r0*132 + c0)       = make_float2(acc[mi][ni][0], acc[mi][ni][1]);
            *reinterpret_cast<float2*>(st + (r0 + 8)*132 + c0) = make_float2(acc[mi][ni][2], acc[mi][ni][3]);
        }
    __syncthreads();
    const float4* bp4 = reinterpret_cast<const float4*>(bkv + slot*256 + nh*128);
    float* dst = Cbuf + (size_t)slot*KVSZ + arow0*256 + nh*128;
#pragma unroll
    for (int it = 0; it < 8; it++){
        int i = tid + it*512;
        int row = i >> 5, q = i & 31;
        float4 v = *reinterpret_cast<float4*>(st + row*132 + q*4);
        float4 bb = bp4[q];
        v.x += bb.x; v.y += bb.y; v.z += bb.z; v.w += bb.w;
        *reinterpret_cast<float4*>(dst + (size_t)row*256 + q*4) = v;
    }
}

// ---- mma.sync small GEMM: C[.,N] = A(hi/lo)[.,256] @ Wt(hi/lo)^T (+bias) ----
__global__ void __launch_bounds__(256) k_qgemm(
    const __nv_bfloat16* __restrict__ Ah, const __nv_bfloat16* __restrict__ Al,
    const __nv_bfloat16* __restrict__ Wh, const __nv_bfloat16* __restrict__ Wl,
    const float* __restrict__ bias, float* __restrict__ C, int ldc)
{
    extern __shared__ char sm[];
    uint32_t sb = smem_u32(sm);
    int tid = threadIdx.x, lane = tid & 31, warp = tid >> 5;
    int mt = blockIdx.x, nt = blockIdx.y;
    size_t arow0 = (size_t)mt * 128;
    const __nv_bfloat16* wh = Wh + (size_t)nt*128*256;
    const __nv_bfloat16* wl = Wl + (size_t)nt*128*256;

    int wm = warp >> 1, wn = warp & 1;

    float acc[2][8][4];
#pragma unroll
    for (int mi = 0; mi < 2; mi++)
#pragma unroll
        for (int ni = 0; ni < 8; ni++)
#pragma unroll
            for (int k = 0; k < 4; k++) acc[mi][ni][k] = 0.f;

    auto prefetch = [&](int ck, int buf){
        uint32_t stage = sb + buf*65536;
#pragma unroll
        for (int it = 0; it < 4; it++){
            int i = tid + it*256;
            int row = i >> 3, g = i & 7;
            uint32_t so = stage + row*128 + (((g ^ (row & 7)) << 4));
            cp16(so,         Ah + (arow0 + row)*256 + ck*64 + g*8);
            cp16(so + 16384, Al + (arow0 + row)*256 + ck*64 + g*8);
            cp16(so + 32768, wh + row*256 + ck*64 + g*8);
            cp16(so + 49152, wl + row*256 + ck*64 + g*8);
        }
        cp_commit();
    };

    prefetch(0, 0);

    for (int ck = 0; ck < 4; ck++){
        int buf = ck & 1;
        if (ck + 1 < 4){ prefetch(ck + 1, (ck + 1) & 1); cp_wait<1>(); }
        else           { cp_wait<0>(); }
        __syncthreads();

        uint32_t stage = sb + buf*65536;
#pragma unroll
        for (int k16 = 0; k16 < 4; k16++){
            int msel = lane >> 3;
            int rsub = (msel & 1)*8 + (lane & 7);
            int gg   = k16*2 + (msel >> 1);
            uint32_t ah[2][4], al[2][4];
#pragma unroll
            for (int mi = 0; mi < 2; mi++){
                int r = wm*32 + mi*16 + rsub;
                uint32_t ad = stage + r*128 + (((gg ^ (r & 7)) << 4));
                ldsm4(ah[mi], ad);
                ldsm4(al[mi], ad + 16384);
            }
            uint32_t bh[4][4], bl[4][4];
#pragma unroll
            for (int nj = 0; nj < 4; nj++){
                int r = wn*64 + nj*16 + rsub;
                uint32_t ad = stage + 32768 + r*128 + (((gg ^ (r & 7)) << 4));
                ldsm4(bh[nj], ad);
                ldsm4(bl[nj], ad + 16384);
            }
#pragma unroll
            for (int mi = 0; mi < 2; mi++)
#pragma unroll
                for (int ni = 0; ni < 8; ni++){
                    int nj = ni >> 1, sel = ni & 1;
                    mma16816(acc[mi][ni], ah[mi], bh[nj][sel], bh[nj][2+sel]);
                    mma16816(acc[mi][ni], ah[mi], bl[nj][sel], bl[nj][2+sel]);
                    mma16816(acc[mi][ni], al[mi], bh[nj][sel], bh[nj][2+sel]);
                }
        }
        __syncthreads();
    }

    int n0 = nt*128;
#pragma unroll
    for (int mi = 0; mi < 2; mi++){
#pragma unroll
        for (int ni = 0; ni < 8; ni++){
            int row = (int)arow0 + wm*32 + mi*16 + (lane >> 2);
            int col = n0 + wn*64 + ni*8 + (lane & 3)*2;
            float bx = bias ? bias[col]     : 0.f;
            float by = bias ? bias[col + 1] : 0.f;
            float2 v0 = make_float2(acc[mi][ni][0] + bx, acc[mi][ni][1] + by);
            float2 v1 = make_float2(acc[mi][ni][2] + bx, acc[mi][ni][3] + by);
            *reinterpret_cast<float2*>(C + (size_t)row*ldc + col) = v0;
            *reinterpret_cast<float2*>(C + (size_t)(row + 8)*ldc + col) = v1;
        }
    }
}

// ---- LN rows of qsa -> bf16 hi/lo ----
__global__ void __launch_bounds__(256) k_lnsplit(const float* __restrict__ in,
    __nv_bfloat16* __restrict__ xh, __nv_bfloat16* __restrict__ xl)
{
    __shared__ float sh[32];
    int row = blockIdx.x, c = threadIdx.x;
    float x = in[(size_t)row*256 + c];
    float m = blockSum(x, sh) * (1.f/256.f);
    float d = x - m;
    float var = blockSum(d*d, sh) * (1.f/256.f);
    float v = d * rsqrtf(var + 1e-5f);
    hilo(v, &xh[(size_t)row*256 + c], &xl[(size_t)row*256 + c]);
}

// ---------------- self-attention over 100 keys, per (h, b, l) ----------------
__global__ void __launch_bounds__(128) k_sa(const float* __restrict__ qkv,
                                            __nv_bfloat16* __restrict__ oh,
                                            __nv_bfloat16* __restrict__ ol){
    __shared__ __align__(16) float sK[100][32];
    __shared__ __align__(16) float sV[100][32];
    int h = blockIdx.x, b = blockIdx.y, l = blockIdx.z;
    int lb = l*4 + b;
    const float* qb = qkv + (size_t)lb*100*768;
    for (int idx = threadIdx.x; idx < 1600; idx += 128){
        int arr = (idx >= 800);
        int rem = arr ? idx - 800 : idx;
        int row = rem >> 3, qd = rem & 7;
        float4 v = *reinterpret_cast<const float4*>(
            qb + (size_t)row*768 + 256 + arr*256 + h*32 + qd*4);
        float* dstp = arr ? &sV[row][qd*4] : &sK[row][qd*4];
        *reinterpret_cast<float4*>(dstp) = v;
    }
    __syncthreads();
    int i = threadIdx.x;
    if (i < 100){
        float Q[32];
        const float4* qp4 = reinterpret_cast<const float4*>(qb + (size_t)i*768 + h*32);
#pragma unroll
        for (int qd = 0; qd < 8; qd++){
            float4 v = qp4[qd];
            Q[qd*4+0] = v.x; Q[qd*4+1] = v.y; Q[qd*4+2] = v.z; Q[qd*4+3] = v.w;
        }
        float m = -1e30f, s = 0.f, acc[32];
#pragma unroll
        for (int c = 0; c < 32; c++) acc[c] = 0.f;
        for (int j = 0; j < 100; j++){
            const float4* k4 = reinterpret_cast<const float4*>(sK[j]);
            float d = 0.f;
#pragma unroll
            for (int qd = 0; qd < 8; qd++){
                float4 kv = k4[qd];
                d = fmaf(Q[qd*4+0], kv.x, d); d = fmaf(Q[qd*4+1], kv.y, d);
                d = fmaf(Q[qd*4+2], kv.z, d); d = fmaf(Q[qd*4+3], kv.w, d);
            }
            d *= 0.17677669529663687f;
            const float4* v4 = reinterpret_cast<const float4*>(sV[j]);
            if (d > m){
                float f = __expf(m - d);
                m = d; s = fmaf(s, f, 1.f);
#pragma unroll
                for (int qd = 0; qd < 8; qd++){
                    float4 vv = v4[qd];
                    acc[qd*4+0] = fmaf(acc[qd*4+0], f, vv.x);
                    acc[qd*4+1] = fmaf(acc[qd*4+1], f, vv.y);
                    acc[qd*4+2] = fmaf(acc[qd*4+2], f, vv.z);
                    acc[qd*4+3] = fmaf(acc[qd*4+3], f, vv.w);
                }
            } else {
                float p = __expf(d - m);
                s += p;
#pragma unroll
                for (int qd = 0; qd < 8; qd++){
                    float4 vv = v4[qd];
                    acc[qd*4+0] = fmaf(p, vv.x, acc[qd*4+0]);
                    acc[qd*4+1] = fmaf(p, vv.y, acc[qd*4+1]);
                    acc[qd*4+2] = fmaf(p, vv.z, acc[qd*4+2]);
                    acc[qd*4+3] = fmaf(p, vv.w, acc[qd*4+3]);
                }
            }
        }
        float inv = 1.f / s;
        size_t ob = (size_t)(lb*100 + i)*256 + h*32;
#pragma unroll
        for (int c = 0; c < 32; c++)
            hilo(acc[c]*inv, &oh[ob + c], &ol[ob + c]);
    }
}

// ---- cross-attention flash partials: 256 threads, lane-pair dim split,
// two-pass 32-key subchunks (scores in regs, one rescale per subchunk) ----
__global__ void __launch_bounds__(256) k_cross(
    const float* __restrict__ qn, const float* __restrict__ Kg,
    const float* __restrict__ Vg, float* __restrict__ pm,
    float* __restrict__ ps, float* __restrict__ pacc)
{
    __shared__ __align__(16) float sKV[2][2][64][32];
    int ss = blockIdx.x, h = blockIdx.y, vb = blockIdx.z;
    int v = vb >> 2, b = vb & 3;
    int l = c_sl[ss];
    int Nl = c_N[l];
    int ck = c_ck[ss];
    int kbeg = c_sk[ss]*ck;
    int lb = l*4 + b;
    size_t kvbase = ((size_t)v*TOKV + c_off[l] + (size_t)b*Nl)*256 + h*32;
    const float* Kp = Kg + kvbase;
    const float* Vp = Vg + kvbase;
    int tid = threadIdx.x;
    int warp = tid >> 5, lane = tid & 31;
    int qi = warp*16 + (lane & 15);     // query 0..127
    int half = lane >> 4;               // dim half
    bool active = qi < 100;
    uint32_t sbase = smem_u32(&sKV[0][0][0][0]);

    auto prefetch = [&](int kc, int buf){
        uint32_t stage = sbase + buf*16384;
#pragma unroll
        for (int it = 0; it < 4; it++){
            int idx = tid + it*256;
            int a = idx >> 9, rem = idx & 511;
            int row = rem >> 3, qd = rem & 7;
            const float* src = (a ? Vp : Kp) + (size_t)(kc + row)*256 + qd*4;
            cp16(stage + a*8192 + row*128 + qd*16, src);
        }
        cp_commit();
    };

    float Q[16];
#pragma unroll
    for (int c = 0; c < 16; c++) Q[c] = 0.f;
    if (active){
        const float4* qp4 = reinterpret_cast<const float4*>(
            qn + (size_t)(lb*100 + qi)*256 + h*32 + half*16);
#pragma unroll
        for (int qd = 0; qd < 4; qd++){
            float4 vq = qp4[qd];
            Q[qd*4+0] = vq.x; Q[qd*4+1] = vq.y; Q[qd*4+2] = vq.z; Q[qd*4+3] = vq.w;
        }
    }
    float m = -1e30f, s = 0.f, acc[16];
#pragma unroll
    for (int c = 0; c < 16; c++) acc[c] = 0.f;

    int nchunks = ck >> 6;
    prefetch(kbeg, 0);
    for (int cki = 0; cki < nchunks; cki++){
        int buf = cki & 1;
        if (cki + 1 < nchunks){ prefetch(kbeg + (cki+1)*64, buf ^ 1); cp_wait<1>(); }
        else                  { cp_wait<0>(); }
        __syncthreads();
#pragma unroll
        for (int sub = 0; sub < 2; sub++){
            // pass 1: 32 independent score dots
            float sc[32];
#pragma unroll
            for (int j = 0; j < 32; j++){
                const float4* k4 = reinterpret_cast<const float4*>(&sKV[buf][0][sub*32 + j][half*16]);
                float d = 0.f;
#pragma unroll
                for (int qd = 0; qd < 4; qd++){
                    float4 kv = k4[qd];
                    d = fmaf(Q[qd*4+0], kv.x, d); d = fmaf(Q[qd*4+1], kv.y, d);
                    d = fmaf(Q[qd*4+2], kv.z, d); d = fmaf(Q[qd*4+3], kv.w, d);
                }
                sc[j] = d;
            }
            // combine halves + scale
            float cmax = -1e30f;
#pragma unroll
            for (int j = 0; j < 32; j++){
                sc[j] += __shfl_xor_sync(0xffffffffu, sc[j], 16);
                sc[j] *= 0.17677669529663687f;
                cmax = fmaxf(cmax, sc[j]);
            }
            // single rescale per subchunk
            float Mn = fmaxf(m, cmax);
            float f = __expf(m - Mn);
            m = Mn;
            s *= f;
#pragma unroll
            for (int c = 0; c < 16; c++) acc[c] *= f;
            float psum = 0.f;
#pragma unroll
            for (int j = 0; j < 32; j++){
                sc[j] = __expf(sc[j] - Mn);
                psum += sc[j];
            }
            s += psum;
            // pass 2: PV
#pragma unroll
            for (int j = 0; j < 32; j++){
                const float4* v4 = reinterpret_cast<const float4*>(&sKV[buf][1][sub*32 + j][half*16]);
                float p = sc[j];
#pragma unroll
                for (int qd = 0; qd < 4; qd++){
                    float4 vv = v4[qd];
                    acc[qd*4+0] = fmaf(p, vv.x, acc[qd*4+0]);
                    acc[qd*4+1] = fmaf(p, vv.y, acc[qd*4+1]);
                    acc[qd*4+2] = fmaf(p, vv.z, acc[qd*4+2]);
                    acc[qd*4+3] = fmaf(p, vv.w, acc[qd*4+3]);
                }
            }
        }
        __syncthreads();
    }
    if (active){
        int slot = (vb*8 + h)*22 + ss;
        if (half == 0){
            pm[slot*100 + qi] = m;
            ps[slot*100 + qi] = s;
        }
        float* pa = pacc + (size_t)(slot*100 + qi)*32 + half*16;
#pragma unroll
        for (int c = 0; c < 16; c++) pa[c] = acc[c];
    }
}

__global__ void __launch_bounds__(128) k_combine(
    const float* __restrict__ pm, const float* __restrict__ ps,
    const float* __restrict__ pacc,
    __nv_bfloat16* __restrict__ och, __nv_bfloat16* __restrict__ ocl)
{
    int l = blockIdx.x, h = blockIdx.y, vb = blockIdx.z;
    int i = threadIdx.x;
    if (i >= 100) return;
    int S = c_S[l], s0 = c_s0[l];
    int base = (vb*8 + h)*22 + s0;
    float M = -1e30f;
    for (int k = 0; k < S; k++) M = fmaxf(M, pm[(base + k)*100 + i]);
    float Ss = 0.f, acc[32];
#pragma unroll
    for (int c = 0; c < 32; c++) acc[c] = 0.f;
    for (int k = 0; k < S; k++){
        int slot = base + k;
        float f = __expf(pm[slot*100 + i] - M);
        Ss = fmaf(ps[slot*100 + i], f, Ss);
        const float* pa = pacc + (size_t)(slot*100 + i)*32;
#pragma unroll
        for (int c = 0; c < 32; c++) acc[c] = fmaf(pa[c], f, acc[c]);
    }
    float inv = 1.f / Ss;
    int v = vb >> 2, b = vb & 3;
    int lb = l*4 + b;
    size_t ob = (size_t)(v*1600 + lb*100 + i)*256 + h*32;
#pragma unroll
    for (int c = 0; c < 32; c++)
        hilo(acc[c]*inv, &och[ob + c], &ocl[ob + c]);
}

// ---- matching score + both softmaxes, one block per lb ----
__global__ void __launch_bounds__(256) k_matchsm(const float* __restrict__ q12,
                                                 float* __restrict__ wr,
                                                 float* __restrict__ wc){
    extern __shared__ float buf[];          // >= 10100 floats
    float* sA = buf;                        // [100][33]
    float* sB = buf + 3300;                 // [100][33]
    int lb = blockIdx.x;
    int tid = threadIdx.x;
    int tx = tid & 15, ty = tid >> 4;
    const float* q1 = q12 + (size_t)lb*25600;
    const float* q2 = q12 + 409600 + (size_t)lb*25600;
    float acc[7][7];
#pragma unroll
    for (int a = 0; a < 7; a++)
#pragma unroll
        for (int bq = 0; bq < 7; bq++) acc[a][bq] = 0.f;
    for (int k0 = 0; k0 < 256; k0 += 32){
        __syncthreads();
        for (int idx = tid; idx < 3200; idx += 256){
            int r = idx >> 5, kk = idx & 31;
            sA[r*33 + kk] = q1[(size_t)r*256 + k0 + kk];
            sB[r*33 + kk] = q2[(size_t)r*256 + k0 + kk];
        }
        __syncthreads();
        for (int kk = 0; kk < 32; kk++){
            float a[7], b[7];
#pragma unroll
            for (int ii = 0; ii < 7; ii++){
                int i = ty + 16*ii;
                a[ii] = (i < 100) ? sA[i*33 + kk] : 0.f;
            }
#pragma unroll
            for (int jj = 0; jj < 7; jj++){
                int j = tx + 16*jj;
                b[jj] = (j < 100) ? sB[j*33 + kk] : 0.f;
            }
#pragma unroll
            for (int ii = 0; ii < 7; ii++)
#pragma unroll
                for (int jj = 0; jj < 7; jj++) acc[ii][jj] = fmaf(a[ii], b[jj], acc[ii][jj]);
        }
    }
    __syncthreads();                        // reuse buf as ms[100][101]
#pragma unroll
    for (int ii = 0; ii < 7; ii++){
        int i = ty + 16*ii;
        if (i < 100){
#pragma unroll
            for (int jj = 0; jj < 7; jj++){
                int j = tx + 16*jj;
                if (j < 100) buf[i*101 + j] = acc[ii][jj];
            }
        }
    }
    __syncthreads();
    int w = tid >> 5, lane = tid & 31;
    for (int r = w; r < 100; r += 8){
        float v0 = buf[r*101 + lane];
        float v1 = buf[r*101 + 32 + lane];
        float v2 = buf[r*101 + 64 + lane];
        float v3 = (lane < 4) ? buf[r*101 + 96 + lane] : -1e30f;
        float M = warpMax(fmaxf(fmaxf(v0, v1), fmaxf(v2, v3)));
        float p0 = __expf(v0 - M), p1 = __expf(v1 - M), p2 = __expf(v2 - M);
        float p3 = (lane < 4) ? __expf(v3 - M) : 0.f;
        float S = warpSum(p0 + p1 + p2 + p3);
        float inv = 1.f / S;
        float* o = wr + (size_t)lb*10000 + r*100;
        o[lane] = p0*inv; o[32 + lane] = p1*inv; o[64 + lane] = p2*inv;
        if (lane < 4) o[96 + lane] = p3*inv;
    }
    for (int cc = w; cc < 100; cc += 8){
        float v0 = buf[lane*101 + cc];
        float v1 = buf[(32 + lane)*101 + cc];
        float v2 = buf[(64 + lane)*101 + cc];
        float v3 = (lane < 4) ? buf[(96 + lane)*101 + cc] : -1e30f;
        float M = warpMax(fmaxf(fmaxf(v0, v1), fmaxf(v2, v3)));
        float p0 = __expf(v0 - M), p1 = __expf(v1 - M), p2 = __expf(v2 - M);
        float p3 = (lane < 4) ? __expf(v3 - M) : 0.f;
        float S = warpSum(p0 + p1 + p2 + p3);
        float inv = 1.f / S;
        float* o = wc + (size_t)lb*10000 + cc;
        o[lane*100] = p0*inv; o[(32 + lane)*100] = p1*inv; o[(64 + lane)*100] = p2*inv;
        if (lane < 4) o[(96 + lane)*100] = p3*inv;
    }
}

// -------- fuse (4 queries/block): t = qsa+q1+q2+Wr@q2+Wc^T@q1; softmax over c ----
__global__ void __launch_bounds__(256) k_fuse(
    const float* __restrict__ qsa, const float* __restrict__ q12,
    const float* __restrict__ wr, const float* __restrict__ wc,
    __nv_bfloat16* __restrict__ qh, __nv_bfloat16* __restrict__ ql,
    float* __restrict__ outp)
{
    __shared__ float swr[4][100];
    __shared__ float swc[4][100];
    __shared__ float sh[32];
    int i0 = blockIdx.x * 4, lb = blockIdx.y, c = threadIdx.x;
    const float* q1 = q12 + (size_t)lb*25600;
    const float* q2 = q12 + 409600 + (size_t)lb*25600;
    for (int idx = c; idx < 400; idx += 256){
        int ii = idx / 100, j = idx % 100;
        swr[ii][j] = wr[(size_t)lb*10000 + (i0+ii)*100 + j];
        swc[ii][j] = wc[(size_t)lb*10000 + j*100 + (i0+ii)];
    }
    __syncthreads();
    float acc[4];
#pragma unroll
    for (int ii = 0; ii < 4; ii++)
        acc[ii] = qsa[(size_t)(lb*100 + i0+ii)*256 + c]
                + q1[(size_t)(i0+ii)*256 + c] + q2[(size_t)(i0+ii)*256 + c];
    for (int j = 0; j < 100; j++){
        float q1v = q1[(size_t)j*256 + c];
        float q2v = q2[(size_t)j*256 + c];
#pragma unroll
        for (int ii = 0; ii < 4; ii++){
            acc[ii] = fmaf(swr[ii][j], q2v, acc[ii]);
            acc[ii] = fmaf(swc[ii][j], q1v, acc[ii]);
        }
    }
#pragma unroll
    for (int ii = 0; ii < 4; ii++){
        float M = blockMax(acc[ii], sh);
        float e = __expf(acc[ii] - M);
        float S = blockSum(e, sh);
        float val = e / S;
        size_t off = (size_t)(lb*100 + i0+ii)*256 + c;
        if (outp) outp[off] = val;
        else      hilo(val, &qh[off], &ql[off]);
    }
}

// ---------------- host ----------------
extern "C" void kernel_launch(void* const* d_in, const int* in_sizes, int n_in,
                              void* d_out, int out_size)
{
    float* arena;   cudaGetSymbolAddress((void**)&arena, g_buf);
    float* kvbuf;   cudaGetSymbolAddress((void**)&kvbuf, g_kv);
    __nv_bfloat16 *ahi, *alo, *whi, *wlo;
    cudaGetSymbolAddress((void**)&ahi, g_ahi);
    cudaGetSymbolAddress((void**)&alo, g_alo);
    cudaGetSymbolAddress((void**)&whi, g_whi);
    cudaGetSymbolAddress((void**)&wlo, g_wlo);
    float* bkv;     cudaGetSymbolAddress((void**)&bkv, g_bkv);
    __nv_bfloat16 *qh, *ql, *oh, *ol, *xh, *xl, *och, *ocl;
    cudaGetSymbolAddress((void**)&qh, g_qh);   cudaGetSymbolAddress((void**)&ql, g_ql);
    cudaGetSymbolAddress((void**)&oh, g_oh);   cudaGetSymbolAddress((void**)&ol, g_ol);
    cudaGetSymbolAddress((void**)&xh, g_xh);   cudaGetSymbolAddress((void**)&xl, g_xl);
    cudaGetSymbolAddress((void**)&och, g_och); cudaGetSymbolAddress((void**)&ocl, g_ocl);
    __nv_bfloat16 *wqkvh, *wqkvl, *wswh, *wswl, *wqh2, *wql2, *wph, *wpl;
    cudaGetSymbolAddress((void**)&wqkvh, g_wqkvh); cudaGetSymbolAddress((void**)&wqkvl, g_wqkvl);
    cudaGetSymbolAddress((void**)&wswh, g_wswh);   cudaGetSymbolAddress((void**)&wswl, g_wswl);
    cudaGetSymbolAddress((void**)&wqh2, g_wqh);    cudaGetSymbolAddress((void**)&wql2, g_wql);
    cudaGetSymbolAddress((void**)&wph, g_wph);     cudaGetSymbolAddress((void**)&wpl, g_wpl);
    float *bsw, *bwq, *bwp;
    cudaGetSymbolAddress((void**)&bsw, g_bsw);
    cudaGetSymbolAddress((void**)&bwq, g_bwq);
    cudaGetSymbolAddress((void**)&bwp, g_bwp);

    float* qkv  = arena;                 // 1,277,952 (1664*768)
    float* qsa  = arena + 1277952;       // 425,984
    float* qn   = arena + 1703936;       // 425,984
    float* q12  = arena + 2129920;       // 819,200
    float* wr   = arena + 2949120;       // 160,000
    float* wc   = arena + 3109120;       // 160,000
    float* pm   = arena + 3269120;       // 140,800
    float* ps   = arena + 3409920;       // 140,800
    float* pacc = arena + 3550720;       // 4,505,600

    FeatPtrs fp;
    for (int i = 0; i < 8; i++) fp.p[i] = (const float*)d_in[i];
    const float* qe   = (const float*)d_in[8];
    const float* ng   = (const float*)d_in[9];
    const float* nb   = (const float*)d_in[10];
    const float* wq   = (const float*)d_in[11];
    const float* wk   = (const float*)d_in[12];
    const float* wv   = (const float*)d_in[13];
    const float* wp   = (const float*)d_in[14];
    const float* bp   = (const float*)d_in[15];
    const float* wqkv = (const float*)d_in[16];
    const float* swp  = (const float*)d_in[17];
    const float* sbp  = (const float*)d_in[18];

    cudaFuncSetAttribute(k_kvgemm, cudaFuncAttributeMaxDynamicSharedMemorySize, 131072);
    cudaFuncSetAttribute(k_qgemm,  cudaFuncAttributeMaxDynamicSharedMemorySize, 131072);

    k_init_q<<<1600, 256>>>(qe, qh, ql);
    k_tok_ln<<<dim3(680, 2), 256>>>(fp, ahi, alo);
    k_prep_w<<<12, 256>>>(wk, wv, ng, nb, whi, wlo, bkv);
    k_kvgemm<<<dim3(12, 2, 340), 512, 131072>>>(ahi, alo, whi, wlo, bkv, kvbuf); // profiled
    k_prep_wt<<<dim3(3, 6), 256>>>(wqkv, nullptr, nullptr, nullptr, wqkvh, wqkvl, nullptr, 768);
    k_prep_wt<<<dim3(1, 6), 256>>>(swp, nullptr, nullptr, sbp, wswh, wswl, bsw, 256);
    k_prep_wt<<<dim3(1, 6), 256>>>(wq, ng, nb, nullptr, wqh2, wql2, bwq, 256);
    k_prep_wt<<<dim3(1, 6), 256>>>(wp, nullptr, nullptr, bp, wph, wpl, bwp, 256);

    for (int d = 0; d < 6; d++){
        k_qgemm<<<dim3(13, 6), 256, 131072>>>(qh, ql,
            wqkvh + (size_t)d*768*256, wqkvl + (size_t)d*768*256,
            nullptr, qkv, 768);
        k_sa<<<dim3(8, 4, 4), 128>>>(qkv, oh, ol);
        k_qgemm<<<dim3(13, 2), 256, 131072>>>(oh, ol,
            wswh + (size_t)d*65536, wswl + (size_t)d*65536,
            bsw + d*256, qsa, 256);
        k_lnsplit<<<1600, 256>>>(qsa, xh, xl);
        k_qgemm<<<dim3(13, 2), 256, 131072>>>(xh, xl,
            wqh2 + (size_t)d*65536, wql2 + (size_t)d*65536,
            bwq + d*256, qn, 256);
        k_cross<<<dim3(22, 8, 8), 256>>>(qn, kvbuf + (size_t)(2*d)*KVSZ,
                                         kvbuf + (size_t)(2*d+1)*KVSZ, pm, ps, pacc);
        k_combine<<<dim3(4, 8, 8), 128>>>(pm, ps, pacc, och, ocl);
        k_qgemm<<<dim3(25, 2), 256, 131072>>>(och, ocl,
            wph + (size_t)d*65536, wpl + (size_t)d*65536,
            bwp + d*256, q12, 256);
        k_matchsm<<<16, 256, 10100*sizeof(float)>>>(q12, wr, wc);
        k_fuse<<<dim3(25, 16), 256>>>(qsa, q12, wr, wc, qh, ql,
                                      (d == 5) ? (float*)d_out : nullptr);
    }
}

// round 15
// speedup vs baseline: 1.6647x; 1.2491x over previous
#include <cuda_runtime.h>
#include <cuda_bf16.h>
#include <cstdint>
#include <math.h>

#define TOKV 21760            // per-view feature tokens: 4*(4096+1024+256+64)
#define AROWS 43520           // 2 views
#define KVSZ  11141120        // 43520*256 (elements)
#define MPAD  1664            // 1600 padded to 13*128

__constant__ int c_N[4]   = {4096, 1024, 256, 64};
__constant__ int c_off[4] = {0, 16384, 20480, 21504};
// 22 cross-attn split slots (256-key chunks; level 3 has 64)
__constant__ int c_sl[22] = {0,0,0,0,0,0,0,0,0,0,0,0,0,0,0,0, 1,1,1,1, 2, 3};
__constant__ int c_sk[22] = {0,1,2,3,4,5,6,7,8,9,10,11,12,13,14,15, 0,1,2,3, 0, 0};
__constant__ int c_ck[22] = {256,256,256,256,256,256,256,256,256,256,256,256,256,256,256,256,
                             256,256,256,256, 256, 64};
__constant__ int c_S[4]  = {16,4,1,1};
__constant__ int c_s0[4] = {0,16,20,21};

// ---- device scratch (allocations forbidden) ----
__device__ float g_kv[12*KVSZ];                 // reused as bf16 kvh | kvl
__device__ __nv_bfloat16 g_ahi[AROWS*256];
__device__ __nv_bfloat16 g_alo[AROWS*256];
__device__ __nv_bfloat16 g_whi[12*256*256];
__device__ __nv_bfloat16 g_wlo[12*256*256];
__device__ float g_bkv[12*256];
__device__ __nv_bfloat16 g_qh[MPAD*256],  g_ql[MPAD*256];
__device__ __nv_bfloat16 g_oh[MPAD*256],  g_ol[MPAD*256];
__device__ __nv_bfloat16 g_xh[MPAD*256],  g_xl[MPAD*256];
__device__ __nv_bfloat16 g_qnh[MPAD*256], g_qnl[MPAD*256];
__device__ __nv_bfloat16 g_och[3200*256], g_ocl[3200*256];
__device__ __nv_bfloat16 g_wqkvh[6*768*256], g_wqkvl[6*768*256];
__device__ __nv_bfloat16 g_wswh[6*256*256],  g_wswl[6*256*256];
__device__ __nv_bfloat16 g_wqh[6*256*256],   g_wql[6*256*256];
__device__ __nv_bfloat16 g_wph[6*256*256],   g_wpl[6*256*256];
__device__ float g_bsw[1536], g_bwq[1536], g_bwp[1536];
__device__ float g_buf[9000000];

struct FeatPtrs { const float* p[8]; };

// ---------------- PTX helpers ----------------
__device__ __forceinline__ uint32_t smem_u32(const void* p){
    uint32_t a;
    asm("{ .reg .u64 t; cvta.to.shared.u64 t, %1; cvt.u32.u64 %0, t; }" : "=r"(a) : "l"(p));
    return a;
}
__device__ __forceinline__ void cp16(uint32_t s, const void* g){
    asm volatile("cp.async.cg.shared.global [%0], [%1], 16;" :: "r"(s), "l"(g) : "memory");
}
__device__ __forceinline__ void cp_commit(){
    asm volatile("cp.async.commit_group;" ::: "memory");
}
template<int N>
__device__ __forceinline__ void cp_wait(){
    asm volatile("cp.async.wait_group %0;" :: "n"(N) : "memory");
}
__device__ __forceinline__ void ldsm4(uint32_t* r, uint32_t a){
    asm volatile("ldmatrix.sync.aligned.m8n8.x4.shared.b16 {%0,%1,%2,%3}, [%4];"
                 : "=r"(r[0]), "=r"(r[1]), "=r"(r[2]), "=r"(r[3]) : "r"(a));
}
__device__ __forceinline__ void ldsm4t(uint32_t* r, uint32_t a){
    asm volatile("ldmatrix.sync.aligned.m8n8.x4.trans.shared.b16 {%0,%1,%2,%3}, [%4];"
                 : "=r"(r[0]), "=r"(r[1]), "=r"(r[2]), "=r"(r[3]) : "r"(a));
}
__device__ __forceinline__ void mma16816(float* c, const uint32_t* a,
                                         uint32_t b0, uint32_t b1){
    asm volatile(
        "mma.sync.aligned.m16n8k16.row.col.f32.bf16.bf16.f32 "
        "{%0,%1,%2,%3}, {%4,%5,%6,%7}, {%8,%9}, {%0,%1,%2,%3};"
        : "+f"(c[0]), "+f"(c[1]), "+f"(c[2]), "+f"(c[3])
        : "r"(a[0]), "r"(a[1]), "r"(a[2]), "r"(a[3]), "r"(b0), "r"(b1));
}
__device__ __forceinline__ void hilo(float v, __nv_bfloat16* ph, __nv_bfloat16* pl){
    __nv_bfloat16 h = __float2bfloat16(v);
    *ph = h;
    *pl = __float2bfloat16(v - __bfloat162float(h));
}
__device__ __forceinline__ uint32_t pack2(float a, float b){
    __nv_bfloat16 h0 = __float2bfloat16(a);
    __nv_bfloat16 h1 = __float2bfloat16(b);
    return (uint32_t)__bfloat16_as_ushort(h0) | ((uint32_t)__bfloat16_as_ushort(h1) << 16);
}
__device__ __forceinline__ uint32_t pack2r(float a, float b){
    __nv_bfloat16 h0 = __float2bfloat16(a);
    __nv_bfloat16 h1 = __float2bfloat16(b);
    float r0 = a - __bfloat162float(h0);
    float r1 = b - __bfloat162float(h1);
    return pack2(r0, r1);
}

// ---------------- reductions ----------------
__device__ __forceinline__ float warpSum(float v){
#pragma unroll
    for (int o = 16; o > 0; o >>= 1) v += __shfl_xor_sync(0xffffffffu, v, o);
    return v;
}
__device__ __forceinline__ float warpMax(float v){
#pragma unroll
    for (int o = 16; o > 0; o >>= 1) v = fmaxf(v, __shfl_xor_sync(0xffffffffu, v, o));
    return v;
}
__device__ __forceinline__ float blockSum(float v, float* sh){
    int lane = threadIdx.x & 31, w = threadIdx.x >> 5;
    int nw = blockDim.x >> 5;
    __syncthreads();
    v = warpSum(v);
    if (lane == 0) sh[w] = v;
    __syncthreads();
    if (w == 0){
        float r = (threadIdx.x < nw) ? sh[threadIdx.x] : 0.f;
        r = warpSum(r);
        if (lane == 0) sh[0] = r;
    }
    __syncthreads();
    return sh[0];
}
__device__ __forceinline__ float blockMax(float v, float* sh){
    int lane = threadIdx.x & 31, w = threadIdx.x >> 5;
    int nw = blockDim.x >> 5;
    __syncthreads();
    v = warpMax(v);
    if (lane == 0) sh[w] = v;
    __syncthreads();
    if (w == 0){
        float r = (threadIdx.x < nw) ? sh[threadIdx.x] : -1e30f;
        r = warpMax(r);
        if (lane == 0) sh[0] = r;
    }
    __syncthreads();
    return sh[0];
}

// ---- tokenize + LN normalization -> bf16 hi/lo ----
__global__ void __launch_bounds__(256) k_tok_ln(FeatPtrs fp,
    __nv_bfloat16* __restrict__ ahi, __nv_bfloat16* __restrict__ alo)
{
    __shared__ float s[256][33];
    __shared__ float ps[8][32], pq[8][32];
    __shared__ float mean[32], rinv[32];
    int r = blockIdx.x, v = blockIdx.y;
    int l = (r < 512) ? 0 : (r < 640) ? 1 : (r < 672) ? 2 : 3;
    int off32 = (l == 0) ? 0 : (l == 1) ? 512 : (l == 2) ? 640 : 672;
    int Nl = c_N[l];
    int idx = r - off32;
    int tpb = Nl >> 5;
    int b = idx / tpb, t0 = (idx % tpb) * 32;
    const float* f = fp.p[v*4 + l];
    int g = threadIdx.x >> 5, t = threadIdx.x & 31;
    for (int cc = g; cc < 256; cc += 8)
        s[cc][t] = f[((size_t)(b*256 + cc))*Nl + t0 + t];
    __syncthreads();
    float sx = 0.f, sq = 0.f;
#pragma unroll
    for (int k = 0; k < 32; k++){
        float x = s[g*32 + k][t];
        sx += x; sq = fmaf(x, x, sq);
    }
    ps[g][t] = sx; pq[g][t] = sq;
    __syncthreads();
    if (threadIdx.x < 32){
        float m = 0.f, qq = 0.f;
#pragma unroll
        for (int gg = 0; gg < 8; gg++){ m += ps[gg][threadIdx.x]; qq += pq[gg][threadIdx.x]; }
        m *= (1.f/256.f);
        float var = qq*(1.f/256.f) - m*m;
        mean[threadIdx.x] = m;
        rinv[threadIdx.x] = rsqrtf(var + 1e-5f);
    }
    __syncthreads();
    int c = threadIdx.x;
    size_t rowbase = (size_t)v*TOKV + c_off[l] + (size_t)b*Nl + t0;
    for (int tt = 0; tt < 32; tt++){
        float val = (s[c][tt] - mean[tt]) * rinv[tt];
        hilo(val, &ahi[(rowbase + tt)*256 + c], &alo[(rowbase + tt)*256 + c]);
    }
}

// ---- prep KV weights: Wt[n][k] = g[k]*W[k][n] bf16 hi/lo; bias'[n] = b@W ----
__global__ void __launch_bounds__(256) k_prep_w(
    const float* __restrict__ wk, const float* __restrict__ wv,
    const float* __restrict__ ng, const float* __restrict__ nb,
    __nv_bfloat16* __restrict__ whi, __nv_bfloat16* __restrict__ wlo,
    float* __restrict__ bkv)
{
    int s = blockIdx.x, n = threadIdx.x;
    int d = s >> 1;
    const float* W = ((s & 1) ? wv : wk) + (size_t)d*65536;
    const float* g = ng + d*256;
    const float* b = nb + d*256;
    float bias = 0.f;
    size_t obase = ((size_t)s*256 + n)*256;
    for (int k = 0; k < 256; k++){
        float w0 = W[k*256 + n];
        bias = fmaf(b[k], w0, bias);
        float w = g[k]*w0;
        hilo(w, &whi[obase + k], &wlo[obase + k]);
    }
    bkv[s*256 + n] = bias;
}

// ---- generic weight prep (+scale fold) ----
__global__ void __launch_bounds__(256) k_prep_wt(
    const float* __restrict__ W, const float* __restrict__ g,
    const float* __restrict__ bf, const float* __restrict__ ab,
    __nv_bfloat16* __restrict__ wh, __nv_bfloat16* __restrict__ wl,
    float* __restrict__ bo, int N, float scale)
{
    int d = blockIdx.y;
    int n = blockIdx.x*256 + threadIdx.x;
    const float* Wd = W + (size_t)d*256*N;
    float bias = ab ? ab[(size_t)d*N + n] : 0.f;
    size_t ob = ((size_t)d*N + n)*256;
    for (int k = 0; k < 256; k++){
        float w0 = Wd[(size_t)k*N + n];
        if (bf) bias = fmaf(bf[d*256 + k], w0, bias);
        float w = (g ? g[d*256 + k]*w0 : w0) * scale;
        hilo(w, &wh[ob + k], &wl[ob + k]);
    }
    if (bo) bo[(size_t)d*N + n] = bias * scale;
}

__global__ void k_init_q(const float* __restrict__ qe,
                         __nv_bfloat16* __restrict__ qh,
                         __nv_bfloat16* __restrict__ ql){
    int row = blockIdx.x, c = threadIdx.x;
    float val = qe[(row % 100)*256 + c];
    hilo(val, &qh[(size_t)row*256 + c], &ql[(size_t)row*256 + c]);
}

// ---- mma.sync KV GEMM, 512 threads. grid (12 slots, 2 nh, 340 mtiles).
// Writes C as bf16 hi/lo (for tensor-core cross attention).
__global__ void __launch_bounds__(512) k_kvgemm(
    const __nv_bfloat16* __restrict__ Ahi, const __nv_bfloat16* __restrict__ Alo,
    const __nv_bfloat16* __restrict__ Whi, const __nv_bfloat16* __restrict__ Wlo,
    const float* __restrict__ bkv,
    __nv_bfloat16* __restrict__ kvh, __nv_bfloat16* __restrict__ kvl)
{
    extern __shared__ char sm[];
    uint32_t sb = smem_u32(sm);
    int tid = threadIdx.x, lane = tid & 31, warp = tid >> 5;
    int slot = blockIdx.x, nh = blockIdx.y, mt = blockIdx.z;
    size_t arow0 = (size_t)mt * 128;
    const __nv_bfloat16* wh = Whi + (size_t)slot*65536 + (size_t)nh*128*256;
    const __nv_bfloat16* wl = Wlo + (size_t)slot*65536 + (size_t)nh*128*256;

    int wm = warp >> 2, wn = warp & 3;           // warp tile: 32m x 32n

    float acc[2][4][4];
#pragma unroll
    for (int mi = 0; mi < 2; mi++)
#pragma unroll
        for (int ni = 0; ni < 4; ni++)
#pragma unroll
            for (int k = 0; k < 4; k++) acc[mi][ni][k] = 0.f;

    auto prefetch = [&](int ck, int buf){
        uint32_t stage = sb + buf*65536;
#pragma unroll
        for (int it = 0; it < 2; it++){
            int i = tid + it*512;
            int row = i >> 3, g = i & 7;
            uint32_t so = stage + row*128 + (((g ^ (row & 7)) << 4));
            cp16(so,         Ahi + (arow0 + row)*256 + ck*64 + g*8);
            cp16(so + 16384, Alo + (arow0 + row)*256 + ck*64 + g*8);
            cp16(so + 32768, wh + row*256 + ck*64 + g*8);
            cp16(so + 49152, wl + row*256 + ck*64 + g*8);
        }
        cp_commit();
    };

    prefetch(0, 0);

    for (int ck = 0; ck < 4; ck++){
        int buf = ck & 1;
        if (ck + 1 < 4){ prefetch(ck + 1, (ck + 1) & 1); cp_wait<1>(); }
        else           { cp_wait<0>(); }
        __syncthreads();

        uint32_t stage = sb + buf*65536;
#pragma unroll
        for (int k16 = 0; k16 < 4; k16++){
            int msel = lane >> 3;
            int rsub = (msel & 1)*8 + (lane & 7);
            int gg   = k16*2 + (msel >> 1);
            uint32_t ah[2][4], al[2][4];
#pragma unroll
            for (int mi = 0; mi < 2; mi++){
                int r = wm*32 + mi*16 + rsub;
                uint32_t ad = stage + r*128 + (((gg ^ (r & 7)) << 4));
                ldsm4(ah[mi], ad);
                ldsm4(al[mi], ad + 16384);
            }
            uint32_t bh[2][4], bl[2][4];
#pragma unroll
            for (int nj = 0; nj < 2; nj++){
                int r = wn*32 + nj*16 + rsub;
                uint32_t ad = stage + 32768 + r*128 + (((gg ^ (r & 7)) << 4));
                ldsm4(bh[nj], ad);
                ldsm4(bl[nj], ad + 16384);
            }
#pragma unroll
            for (int mi = 0; mi < 2; mi++)
#pragma unroll
                for (int ni = 0; ni < 4; ni++){
                    int nj = ni >> 1, sel = ni & 1;
                    mma16816(acc[mi][ni], ah[mi], bh[nj][sel], bh[nj][2+sel]);
                    mma16816(acc[mi][ni], ah[mi], bl[nj][sel], bl[nj][2+sel]);
                    mma16816(acc[mi][ni], al[mi], bh[nj][sel], bh[nj][2+sel]);
                }
        }
        __syncthreads();
    }

    float* st = reinterpret_cast<float*>(sm);
#pragma unroll
    for (int mi = 0; mi < 2; mi++)
#pragma unroll
        for (int ni = 0; ni < 4; ni++){
            int r0 = wm*32 + mi*16 + (lane >> 2);
            int c0 = wn*32 + ni*8 + (lane & 3)*2;
            *reinterpret_cast<float2*>(st + r0*132 + c0)       = make_float2(acc[mi][ni][0], acc[mi][ni][1]);
            *reinterpret_cast<float2*>(st + (r0 + 8)*132 + c0) = make_float2(acc[mi][ni][2], acc[mi][ni][3]);
        }
    __syncthreads();
    const float* bp = bkv + slot*256 + nh*128;
    __nv_bfloat16* dh = kvh + (size_t)slot*KVSZ + arow0*256 + nh*128;
    __nv_bfloat16* dl = kvl + (size_t)slot*KVSZ + arow0*256 + nh*128;
#pragma unroll
    for (int it = 0; it < 4; it++){
        int i = tid + it*512;              // 2048 slots: 128 rows x 16
        int row = i >> 4, q = i & 15;
        float v0 = st[row*132 + q*8 + 0] + bp[q*8 + 0];
        float v1 = st[row*132 + q*8 + 1] + bp[q*8 + 1];
        float v2 = st[row*132 + q*8 + 2] + bp[q*8 + 2];
        float v3 = st[row*132 + q*8 + 3] + bp[q*8 + 3];
        float v4 = st[row*132 + q*8 + 4] + bp[q*8 + 4];
        float v5 = st[row*132 + q*8 + 5] + bp[q*8 + 5];
        float v6 = st[row*132 + q*8 + 6] + bp[q*8 + 6];
        float v7 = st[row*132 + q*8 + 7] + bp[q*8 + 7];
        uint4 hh = make_uint4(pack2(v0,v1), pack2(v2,v3), pack2(v4,v5), pack2(v6,v7));
        uint4 ll = make_uint4(pack2r(v0,v1), pack2r(v2,v3), pack2r(v4,v5), pack2r(v6,v7));
        *reinterpret_cast<uint4*>(dh + (size_t)row*256 + q*8) = hh;
        *reinterpret_cast<uint4*>(dl + (size_t)row*256 + q*8) = ll;
    }
}

// ---- mma.sync small GEMM: C = A(hi/lo) @ Wt(hi/lo)^T (+bias); fp32 or bf16 hi/lo out
__global__ void __launch_bounds__(256) k_qgemm(
    const __nv_bfloat16* __restrict__ Ah, const __nv_bfloat16* __restrict__ Al,
    const __nv_bfloat16* __restrict__ Wh, const __nv_bfloat16* __restrict__ Wl,
    const float* __restrict__ bias, float* __restrict__ C, int ldc,
    __nv_bfloat16* __restrict__ Oh, __nv_bfloat16* __restrict__ Ol)
{
    extern __shared__ char sm[];
    uint32_t sb = smem_u32(sm);
    int tid = threadIdx.x, lane = tid & 31, warp = tid >> 5;
    int mt = blockIdx.x, nt = blockIdx.y;
    size_t arow0 = (size_t)mt * 128;
    const __nv_bfloat16* wh = Wh + (size_t)nt*128*256;
    const __nv_bfloat16* wl = Wl + (size_t)nt*128*256;

    int wm = warp >> 1, wn = warp & 1;

    float acc[2][8][4];
#pragma unroll
    for (int mi = 0; mi < 2; mi++)
#pragma unroll
        for (int ni = 0; ni < 8; ni++)
#pragma unroll
            for (int k = 0; k < 4; k++) acc[mi][ni][k] = 0.f;

    auto prefetch = [&](int ck, int buf){
        uint32_t stage = sb + buf*65536;
#pragma unroll
        for (int it = 0; it < 4; it++){
            int i = tid + it*256;
            int row = i >> 3, g = i & 7;
            uint32_t so = stage + row*128 + (((g ^ (row & 7)) << 4));
            cp16(so,         Ah + (arow0 + row)*256 + ck*64 + g*8);
            cp16(so + 16384, Al + (arow0 + row)*256 + ck*64 + g*8);
            cp16(so + 32768, wh + row*256 + ck*64 + g*8);
            cp16(so + 49152, wl + row*256 + ck*64 + g*8);
        }
        cp_commit();
    };

    prefetch(0, 0);

    for (int ck = 0; ck < 4; ck++){
        int buf = ck & 1;
        if (ck + 1 < 4){ prefetch(ck + 1, (ck + 1) & 1); cp_wait<1>(); }
        else           { cp_wait<0>(); }
        __syncthreads();

        uint32_t stage = sb + buf*65536;
#pragma unroll
        for (int k16 = 0; k16 < 4; k16++){
            int msel = lane >> 3;
            int rsub = (msel & 1)*8 + (lane & 7);
            int gg   = k16*2 + (msel >> 1);
            uint32_t ah[2][4], al[2][4];
#pragma unroll
            for (int mi = 0; mi < 2; mi++){
                int r = wm*32 + mi*16 + rsub;
                uint32_t ad = stage + r*128 + (((gg ^ (r & 7)) << 4));
                ldsm4(ah[mi], ad);
                ldsm4(al[mi], ad + 16384);
            }
            uint32_t bh[4][4], bl[4][4];
#pragma unroll
            for (int nj = 0; nj < 4; nj++){
                int r = wn*64 + nj*16 + rsub;
                uint32_t ad = stage + 32768 + r*128 + (((gg ^ (r & 7)) << 4));
                ldsm4(bh[nj], ad);
                ldsm4(bl[nj], ad + 16384);
            }
#pragma unroll
            for (int mi = 0; mi < 2; mi++)
#pragma unroll
                for (int ni = 0; ni < 8; ni++){
                    int nj = ni >> 1, sel = ni & 1;
                    mma16816(acc[mi][ni], ah[mi], bh[nj][sel], bh[nj][2+sel]);
                    mma16816(acc[mi][ni], ah[mi], bl[nj][sel], bl[nj][2+sel]);
                    mma16816(acc[mi][ni], al[mi], bh[nj][sel], bh[nj][2+sel]);
                }
        }
        __syncthreads();
    }

    int n0 = nt*128;
#pragma unroll
    for (int mi = 0; mi < 2; mi++){
#pragma unroll
        for (int ni = 0; ni < 8; ni++){
            int row = (int)arow0 + wm*32 + mi*16 + (lane >> 2);
            int col = n0 + wn*64 + ni*8 + (lane & 3)*2;
            float bx = bias ? bias[col]     : 0.f;
            float by = bias ? bias[col + 1] : 0.f;
            float v0 = acc[mi][ni][0] + bx, v1 = acc[mi][ni][1] + by;
            float v2 = acc[mi][ni][2] + bx, v3 = acc[mi][ni][3] + by;
            if (Oh){
                *reinterpret_cast<uint32_t*>(Oh + (size_t)row*ldc + col)       = pack2(v0, v1);
                *reinterpret_cast<uint32_t*>(Ol + (size_t)row*ldc + col)       = pack2r(v0, v1);
                *reinterpret_cast<uint32_t*>(Oh + (size_t)(row + 8)*ldc + col) = pack2(v2, v3);
                *reinterpret_cast<uint32_t*>(Ol + (size_t)(row + 8)*ldc + col) = pack2r(v2, v3);
            } else {
                *reinterpret_cast<float2*>(C + (size_t)row*ldc + col) = make_float2(v0, v1);
                *reinterpret_cast<float2*>(C + (size_t)(row + 8)*ldc + col) = make_float2(v2, v3);
            }
        }
    }
}

// ---- LN rows of qsa -> bf16 hi/lo ----
__global__ void __launch_bounds__(256) k_lnsplit(const float* __restrict__ in,
    __nv_bfloat16* __restrict__ xh, __nv_bfloat16* __restrict__ xl)
{
    __shared__ float sh[32];
    int row = blockIdx.x, c = threadIdx.x;
    float x = in[(size_t)row*256 + c];
    float m = blockSum(x, sh) * (1.f/256.f);
    float d = x - m;
    float var = blockSum(d*d, sh) * (1.f/256.f);
    float v = d * rsqrtf(var + 1e-5f);
    hilo(v, &xh[(size_t)row*256 + c], &xl[(size_t)row*256 + c]);
}

// ---------------- self-attention over 100 keys, per (h, b, l) ----------------
__global__ void __launch_bounds__(128) k_sa(const float* __restrict__ qkv,
                                            __nv_bfloat16* __restrict__ oh,
                                            __nv_bfloat16* __restrict__ ol){
    __shared__ __align__(16) float sK[100][32];
    __shared__ __align__(16) float sV[100][32];
    int h = blockIdx.x, b = blockIdx.y, l = blockIdx.z;
    int lb = l*4 + b;
    const float* qb = qkv + (size_t)lb*100*768;
    for (int idx = threadIdx.x; idx < 1600; idx += 128){
        int arr = (idx >= 800);
        int rem = arr ? idx - 800 : idx;
        int row = rem >> 3, qd = rem & 7;
        float4 v = *reinterpret_cast<const float4*>(
            qb + (size_t)row*768 + 256 + arr*256 + h*32 + qd*4);
        float* dstp = arr ? &sV[row][qd*4] : &sK[row][qd*4];
        *reinterpret_cast<float4*>(dstp) = v;
    }
    __syncthreads();
    int i = threadIdx.x;
    if (i < 100){
        float Q[32];
        const float4* qp4 = reinterpret_cast<const float4*>(qb + (size_t)i*768 + h*32);
#pragma unroll
        for (int qd = 0; qd < 8; qd++){
            float4 v = qp4[qd];
            Q[qd*4+0] = v.x; Q[qd*4+1] = v.y; Q[qd*4+2] = v.z; Q[qd*4+3] = v.w;
        }
        float m = -1e30f, s = 0.f, acc[32];
#pragma unroll
        for (int c = 0; c < 32; c++) acc[c] = 0.f;
        for (int j = 0; j < 100; j++){
            const float4* k4 = reinterpret_cast<const float4*>(sK[j]);
            float d = 0.f;
#pragma unroll
            for (int qd = 0; qd < 8; qd++){
                float4 kv = k4[qd];
                d = fmaf(Q[qd*4+0], kv.x, d); d = fmaf(Q[qd*4+1], kv.y, d);
                d = fmaf(Q[qd*4+2], kv.z, d); d = fmaf(Q[qd*4+3], kv.w, d);
            }
            d *= 0.17677669529663687f;
            const float4* v4 = reinterpret_cast<const float4*>(sV[j]);
            if (d > m){
                float f = __expf(m - d);
                m = d; s = fmaf(s, f, 1.f);
#pragma unroll
                for (int qd = 0; qd < 8; qd++){
                    float4 vv = v4[qd];
                    acc[qd*4+0] = fmaf(acc[qd*4+0], f, vv.x);
                    acc[qd*4+1] = fmaf(acc[qd*4+1], f, vv.y);
                    acc[qd*4+2] = fmaf(acc[qd*4+2], f, vv.z);
                    acc[qd*4+3] = fmaf(acc[qd*4+3], f, vv.w);
                }
            } else {
                float p = __expf(d - m);
                s += p;
#pragma unroll
                for (int qd = 0; qd < 8; qd++){
                    float4 vv = v4[qd];
                    acc[qd*4+0] = fmaf(p, vv.x, acc[qd*4+0]);
                    acc[qd*4+1] = fmaf(p, vv.y, acc[qd*4+1]);
                    acc[qd*4+2] = fmaf(p, vv.z, acc[qd*4+2]);
                    acc[qd*4+3] = fmaf(p, vv.w, acc[qd*4+3]);
                }
            }
        }
        float inv = 1.f / s;
        size_t ob = (size_t)(lb*100 + i)*256 + h*32;
#pragma unroll
        for (int c = 0; c < 32; c++)
            hilo(acc[c]*inv, &oh[ob + c], &ol[ob + c]);
    }
}

// ---- tensor-core cross-attention flash partials ----
// grid (22 slots, 8 h, 8 vb), 128 threads (4 warps, 32 query rows each).
// smem: Q [128 rows x 128B] @0 (hi 64B | lo 64B per row), KV stages @16384:
//   stage(buf) = 16384 + buf*16384: K rows [64 x 128B] @0, V rows @8192.
__global__ void __launch_bounds__(128) k_cross(
    const __nv_bfloat16* __restrict__ qnh, const __nv_bfloat16* __restrict__ qnl,
    const __nv_bfloat16* __restrict__ Kh, const __nv_bfloat16* __restrict__ Kl,
    const __nv_bfloat16* __restrict__ Vh, const __nv_bfloat16* __restrict__ Vl,
    float* __restrict__ pm, float* __restrict__ ps, float* __restrict__ pacc)
{
    extern __shared__ char sm[];
    uint32_t sb = smem_u32(sm);
    int ss = blockIdx.x, h = blockIdx.y, vb = blockIdx.z;
    int v = vb >> 2, b = vb & 3;
    int l = c_sl[ss];
    int Nl = c_N[l];
    int ck = c_ck[ss];
    int kbeg = c_sk[ss]*c_ck[ss];
    int lb = l*4 + b;
    size_t kvrow0 = (size_t)v*TOKV + c_off[l] + (size_t)b*Nl + kbeg;
    int tid = threadIdx.x, lane = tid & 31, warp = tid >> 5;

    // zero Q pad rows 100..127
    for (int idx = tid; idx < 896; idx += 128)
        *reinterpret_cast<uint32_t*>(sm + (100 + (idx >> 5))*128 + (idx & 31)*4) = 0;
    // load Q rows 0..99 (hi groups 0-3, lo groups 4-7)
    for (int idx = tid; idx < 800; idx += 128){
        int row = idx >> 3, g = idx & 7;
        const __nv_bfloat16* src = (g < 4)
            ? qnh + (size_t)(lb*100 + row)*256 + h*32 + g*8
            : qnl + (size_t)(lb*100 + row)*256 + h*32 + (g - 4)*8;
        cp16(sb + row*128 + (((g ^ (row & 7)) << 4)), src);
    }

    auto prefetch = [&](int ci, int buf){
        uint32_t stage = sb + 16384 + buf*16384;
#pragma unroll
        for (int it = 0; it < 8; it++){
            int idx = tid + it*128;
            int arr = idx >> 9, rem = idx & 511;
            int row = rem >> 3, g = rem & 7;
            size_t gr = (kvrow0 + ci*64 + row)*256 + h*32;
            const __nv_bfloat16* src;
            if (arr == 0) src = (g < 4) ? Kh + gr + g*8 : Kl + gr + (g - 4)*8;
            else          src = (g < 4) ? Vh + gr + g*8 : Vl + gr + (g - 4)*8;
            cp16(stage + arr*8192 + row*128 + (((g ^ (row & 7)) << 4)), src);
        }
        cp_commit();
    };
    prefetch(0, 0);   // commits Q + chunk0 together

    int msel = lane >> 3;
    int rsub = (msel & 1)*8 + (lane & 7);

    float m_[4], s_[4], O[2][4][4];
#pragma unroll
    for (int i = 0; i < 4; i++){ m_[i] = -1e30f; s_[i] = 0.f; }
#pragma unroll
    for (int a = 0; a < 2; a++)
#pragma unroll
        for (int n = 0; n < 4; n++)
#pragma unroll
            for (int k = 0; k < 4; k++) O[a][n][k] = 0.f;

    int nchunks = ck >> 6;
    for (int cki = 0; cki < nchunks; cki++){
        int buf = cki & 1;
        if (cki + 1 < nchunks){ prefetch(cki + 1, buf ^ 1); cp_wait<1>(); }
        else                  { cp_wait<0>(); }
        __syncthreads();
        uint32_t Kbase = sb + 16384 + buf*16384;
        uint32_t Vbase = Kbase + 8192;

        // ---- S = Q @ K^T (hi/lo 3-product) ----
        float sacc[2][8][4];
#pragma unroll
        for (int a = 0; a < 2; a++)
#pragma unroll
            for (int n = 0; n < 8; n++)
#pragma unroll
                for (int k = 0; k < 4; k++) sacc[a][n][k] = 0.f;

#pragma unroll
        for (int kf = 0; kf < 2; kf++){
            int gg = kf*2 + (msel >> 1);
            uint32_t qah[2][4], qal[2][4];
#pragma unroll
            for (int mf = 0; mf < 2; mf++){
                int r = warp*32 + mf*16 + rsub;
                ldsm4(qah[mf], sb + r*128 + (((gg ^ (r & 7)) << 4)));
                ldsm4(qal[mf], sb + r*128 + ((((gg + 4) ^ (r & 7)) << 4)));
            }
            uint32_t kbh[4][4], kbl[4][4];
#pragma unroll
            for (int nb = 0; nb < 4; nb++){
                int r = nb*16 + rsub;
                ldsm4(kbh[nb], Kbase + r*128 + (((gg ^ (r & 7)) << 4)));
                ldsm4(kbl[nb], Kbase + r*128 + ((((gg + 4) ^ (r & 7)) << 4)));
            }
#pragma unroll
            for (int mf = 0; mf < 2; mf++)
#pragma unroll
                for (int nb = 0; nb < 4; nb++)
#pragma unroll
                    for (int sel = 0; sel < 2; sel++){
                        mma16816(sacc[mf][nb*2+sel], qah[mf], kbh[nb][sel], kbh[nb][2+sel]);
                        mma16816(sacc[mf][nb*2+sel], qah[mf], kbl[nb][sel], kbl[nb][2+sel]);
                        mma16816(sacc[mf][nb*2+sel], qal[mf], kbh[nb][sel], kbh[nb][2+sel]);
                    }
        }

        // ---- online softmax (scale already folded into Q weights) ----
#pragma unroll
        for (int mf = 0; mf < 2; mf++)
#pragma unroll
            for (int h2 = 0; h2 < 2; h2++){
                int sl = mf*2 + h2;
                int e0 = h2*2, e1 = h2*2 + 1;
                float mx = -1e30f;
#pragma unroll
                for (int nf = 0; nf < 8; nf++)
                    mx = fmaxf(mx, fmaxf(sacc[mf][nf][e0], sacc[mf][nf][e1]));
                mx = fmaxf(mx, __shfl_xor_sync(0xffffffffu, mx, 1));
                mx = fmaxf(mx, __shfl_xor_sync(0xffffffffu, mx, 2));
                float Mn = fmaxf(m_[sl], mx);
                float f = __expf(m_[sl] - Mn);
                m_[sl] = Mn;
                float rs = 0.f;
#pragma unroll
                for (int nf = 0; nf < 8; nf++){
                    float p0 = __expf(sacc[mf][nf][e0] - Mn);
                    float p1 = __expf(sacc[mf][nf][e1] - Mn);
                    sacc[mf][nf][e0] = p0; sacc[mf][nf][e1] = p1;
                    rs += p0 + p1;
                }
                rs += __shfl_xor_sync(0xffffffffu, rs, 1);
                rs += __shfl_xor_sync(0xffffffffu, rs, 2);
                s_[sl] = s_[sl]*f + rs;
#pragma unroll
                for (int nd = 0; nd < 4; nd++){
                    O[mf][nd][e0] *= f;
                    O[mf][nd][e1] *= f;
                }
            }

        // ---- O += P @ V (hi/lo 3-product; V via trans-ldsm) ----
#pragma unroll
        for (int kf = 0; kf < 4; kf++){
            uint32_t vbh[2][4], vbl[2][4];
            int krow = kf*16 + (lane & 15);
            int ngrp = lane >> 4;
#pragma unroll
            for (int dt = 0; dt < 2; dt++){
                int gh = dt*2 + ngrp;
                ldsm4t(vbh[dt], Vbase + krow*128 + (((gh ^ (krow & 7)) << 4)));
                ldsm4t(vbl[dt], Vbase + krow*128 + ((((gh + 4) ^ (krow & 7)) << 4)));
            }
#pragma unroll
            for (int mf = 0; mf < 2; mf++){
                float* c0 = sacc[mf][2*kf];
                float* c1 = sacc[mf][2*kf + 1];
                uint32_t pah[4], pal[4];
                pah[0] = pack2(c0[0], c0[1]);  pah[1] = pack2(c0[2], c0[3]);
                pah[2] = pack2(c1[0], c1[1]);  pah[3] = pack2(c1[2], c1[3]);
                pal[0] = pack2r(c0[0], c0[1]); pal[1] = pack2r(c0[2], c0[3]);
                pal[2] = pack2r(c1[0], c1[1]); pal[3] = pack2r(c1[2], c1[3]);
#pragma unroll
                for (int dt = 0; dt < 2; dt++)
#pragma unroll
                    for (int sel = 0; sel < 2; sel++){
                        mma16816(O[mf][dt*2+sel], pah, vbh[dt][sel*2], vbh[dt][sel*2+1]);
                        mma16816(O[mf][dt*2+sel], pah, vbl[dt][sel*2], vbl[dt][sel*2+1]);
                        mma16816(O[mf][dt*2+sel], pal, vbh[dt][sel*2], vbh[dt][sel*2+1]);
                    }
            }
        }
        __syncthreads();
    }

    // ---- write partials ----
    int slot = (vb*8 + h)*22 + ss;
#pragma unroll
    for (int mf = 0; mf < 2; mf++)
#pragma unroll
        for (int h2 = 0; h2 < 2; h2++){
            int row = warp*32 + mf*16 + (lane >> 2) + h2*8;
            if (row < 100){
                int sl = mf*2 + h2;
                if ((lane & 3) == 0){
                    pm[slot*100 + row] = m_[sl];
                    ps[slot*100 + row] = s_[sl];
                }
                float* pa = pacc + (size_t)(slot*100 + row)*32;
#pragma unroll
                for (int nd = 0; nd < 4; nd++){
                    int col = nd*8 + (lane & 3)*2;
                    *reinterpret_cast<float2*>(pa + col) =
                        make_float2(O[mf][nd][h2*2], O[mf][nd][h2*2+1]);
                }
            }
        }
}

__global__ void __launch_bounds__(128) k_combine(
    const float* __restrict__ pm, const float* __restrict__ ps,
    const float* __restrict__ pacc,
    __nv_bfloat16* __restrict__ och, __nv_bfloat16* __restrict__ ocl)
{
    int l = blockIdx.x, h = blockIdx.y, vb = blockIdx.z;
    int i = threadIdx.x;
    if (i >= 100) return;
    int S = c_S[l], s0 = c_s0[l];
    int base = (vb*8 + h)*22 + s0;
    float M = -1e30f;
    for (int k = 0; k < S; k++) M = fmaxf(M, pm[(base + k)*100 + i]);
    float Ss = 0.f, acc[32];
#pragma unroll
    for (int c = 0; c < 32; c++) acc[c] = 0.f;
    for (int k = 0; k < S; k++){
        int slot = base + k;
        float f = __expf(pm[slot*100 + i] - M);
        Ss = fmaf(ps[slot*100 + i], f, Ss);
        const float* pa = pacc + (size_t)(slot*100 + i)*32;
#pragma unroll
        for (int c = 0; c < 32; c++) acc[c] = fmaf(pa[c], f, acc[c]);
    }
    float inv = 1.f / Ss;
    int v = vb >> 2, b = vb & 3;
    int lb = l*4 + b;
    size_t ob = (size_t)(v*1600 + lb*100 + i)*256 + h*32;
#pragma unroll
    for (int c = 0; c < 32; c++)
        hilo(acc[c]*inv, &och[ob + c], &ocl[ob + c]);
}

// ---- matching score + both softmaxes, one block per lb ----
__global__ void __launch_bounds__(256) k_matchsm(const float* __restrict__ q12,
                                                 float* __restrict__ wr,
                                                 float* __restrict__ wc){
    extern __shared__ float buf[];          // >= 10100 floats
    float* sA = buf;                        // [100][33]
    float* sB = buf + 3300;                 // [100][33]
    int lb = blockIdx.x;
    int tid = threadIdx.x;
    int tx = tid & 15, ty = tid >> 4;
    const float* q1 = q12 + (size_t)lb*25600;
    const float* q2 = q12 + 409600 + (size_t)lb*25600;
    float acc[7][7];
#pragma unroll
    for (int a = 0; a < 7; a++)
#pragma unroll
        for (int bq = 0; bq < 7; bq++) acc[a][bq] = 0.f;
    for (int k0 = 0; k0 < 256; k0 += 32){
        __syncthreads();
        for (int idx = tid; idx < 3200; idx += 256){
            int r = idx >> 5, kk = idx & 31;
            sA[r*33 + kk] = q1[(size_t)r*256 + k0 + kk];
            sB[r*33 + kk] = q2[(size_t)r*256 + k0 + kk];
        }
        __syncthreads();
        for (int kk = 0; kk < 32; kk++){
            float a[7], b[7];
#pragma unroll
            for (int ii = 0; ii < 7; ii++){
                int i = ty + 16*ii;
                a[ii] = (i < 100) ? sA[i*33 + kk] : 0.f;
            }
#pragma unroll
            for (int jj = 0; jj < 7; jj++){
                int j = tx + 16*jj;
                b[jj] = (j < 100) ? sB[j*33 + kk] : 0.f;
            }
#pragma unroll
            for (int ii = 0; ii < 7; ii++)
#pragma unroll
                for (int jj = 0; jj < 7; jj++) acc[ii][jj] = fmaf(a[ii], b[jj], acc[ii][jj]);
        }
    }
    __syncthreads();                        // reuse buf as ms[100][101]
#pragma unroll
    for (int ii = 0; ii < 7; ii++){
        int i = ty + 16*ii;
        if (i < 100){
#pragma unroll
            for (int jj = 0; jj < 7; jj++){
                int j = tx + 16*jj;
                if (j < 100) buf[i*101 + j] = acc[ii][jj];
            }
        }
    }
    __syncthreads();
    int w = tid >> 5, lane = tid & 31;
    for (int r = w; r < 100; r += 8){
        float v0 = buf[r*101 + lane];
        float v1 = buf[r*101 + 32 + lane];
        float v2 = buf[r*101 + 64 + lane];
        float v3 = (lane < 4) ? buf[r*101 + 96 + lane] : -1e30f;
        float M = warpMax(fmaxf(fmaxf(v0, v1), fmaxf(v2, v3)));
        float p0 = __expf(v0 - M), p1 = __expf(v1 - M), p2 = __expf(v2 - M);
        float p3 = (lane < 4) ? __expf(v3 - M) : 0.f;
        float S = warpSum(p0 + p1 + p2 + p3);
        float inv = 1.f / S;
        float* o = wr + (size_t)lb*10000 + r*100;
        o[lane] = p0*inv; o[32 + lane] = p1*inv; o[64 + lane] = p2*inv;
        if (lane < 4) o[96 + lane] = p3*inv;
    }
    for (int cc = w; cc < 100; cc += 8){
        float v0 = buf[lane*101 + cc];
        float v1 = buf[(32 + lane)*101 + cc];
        float v2 = buf[(64 + lane)*101 + cc];
        float v3 = (lane < 4) ? buf[(96 + lane)*101 + cc] : -1e30f;
        float M = warpMax(fmaxf(fmaxf(v0, v1), fmaxf(v2, v3)));
        float p0 = __expf(v0 - M), p1 = __expf(v1 - M), p2 = __expf(v2 - M);
        float p3 = (lane < 4) ? __expf(v3 - M) : 0.f;
        float S = warpSum(p0 + p1 + p2 + p3);
        float inv = 1.f / S;
        float* o = wc + (size_t)lb*10000 + cc;
        o[lane*100] = p0*inv; o[(32 + lane)*100] = p1*inv; o[(64 + lane)*100] = p2*inv;
        if (lane < 4) o[(96 + lane)*100] = p3*inv;
    }
}

// -------- fuse (4 queries/block): t = qsa+q1+q2+Wr@q2+Wc^T@q1; softmax over c ----
__global__ void __launch_bounds__(256) k_fuse(
    const float* __restrict__ qsa, const float* __restrict__ q12,
    const float* __restrict__ wr, const float* __restrict__ wc,
    __nv_bfloat16* __restrict__ qh, __nv_bfloat16* __restrict__ ql,
    float* __restrict__ outp)
{
    __shared__ float swr[4][100];
    __shared__ float swc[4][100];
    __shared__ float sh[32];
    int i0 = blockIdx.x * 4, lb = blockIdx.y, c = threadIdx.x;
    const float* q1 = q12 + (size_t)lb*25600;
    const float* q2 = q12 + 409600 + (size_t)lb*25600;
    for (int idx = c; idx < 400; idx += 256){
        int ii = idx / 100, j = idx % 100;
        swr[ii][j] = wr[(size_t)lb*10000 + (i0+ii)*100 + j];
        swc[ii][j] = wc[(size_t)lb*10000 + j*100 + (i0+ii)];
    }
    __syncthreads();
    float acc[4];
#pragma unroll
    for (int ii = 0; ii < 4; ii++)
        acc[ii] = qsa[(size_t)(lb*100 + i0+ii)*256 + c]
                + q1[(size_t)(i0+ii)*256 + c] + q2[(size_t)(i0+ii)*256 + c];
    for (int j = 0; j < 100; j++){
        float q1v = q1[(size_t)j*256 + c];
        float q2v = q2[(size_t)j*256 + c];
#pragma unroll
        for (int ii = 0; ii < 4; ii++){
            acc[ii] = fmaf(swr[ii][j], q2v, acc[ii]);
            acc[ii] = fmaf(swc[ii][j], q1v, acc[ii]);
        }
    }
#pragma unroll
    for (int ii = 0; ii < 4; ii++){
        float M = blockMax(acc[ii], sh);
        float e = __expf(acc[ii] - M);
        float S = blockSum(e, sh);
        float val = e / S;
        size_t off = (size_t)(lb*100 + i0+ii)*256 + c;
        if (outp) outp[off] = val;
        else      hilo(val, &qh[off], &ql[off]);
    }
}

// ---------------- host ----------------
extern "C" void kernel_launch(void* const* d_in, const int* in_sizes, int n_in,
                              void* d_out, int out_size)
{
    float* arena;   cudaGetSymbolAddress((void**)&arena, g_buf);
    float* kvraw;   cudaGetSymbolAddress((void**)&kvraw, g_kv);
    __nv_bfloat16* kvh = reinterpret_cast<__nv_bfloat16*>(kvraw);
    __nv_bfloat16* kvl = kvh + (size_t)12*KVSZ;
    __nv_bfloat16 *ahi, *alo, *whi, *wlo;
    cudaGetSymbolAddress((void**)&ahi, g_ahi);
    cudaGetSymbolAddress((void**)&alo, g_alo);
    cudaGetSymbolAddress((void**)&whi, g_whi);
    cudaGetSymbolAddress((void**)&wlo, g_wlo);
    float* bkv;     cudaGetSymbolAddress((void**)&bkv, g_bkv);
    __nv_bfloat16 *qh, *ql, *oh, *ol, *xh, *xl, *qnh, *qnl, *och, *ocl;
    cudaGetSymbolAddress((void**)&qh, g_qh);   cudaGetSymbolAddress((void**)&ql, g_ql);
    cudaGetSymbolAddress((void**)&oh, g_oh);   cudaGetSymbolAddress((void**)&ol, g_ol);
    cudaGetSymbolAddress((void**)&xh, g_xh);   cudaGetSymbolAddress((void**)&xl, g_xl);
    cudaGetSymbolAddress((void**)&qnh, g_qnh); cudaGetSymbolAddress((void**)&qnl, g_qnl);
    cudaGetSymbolAddress((void**)&och, g_och); cudaGetSymbolAddress((void**)&ocl, g_ocl);
    __nv_bfloat16 *wqkvh, *wqkvl, *wswh, *wswl, *wqh2, *wql2, *wph, *wpl;
    cudaGetSymbolAddress((void**)&wqkvh, g_wqkvh); cudaGetSymbolAddress((void**)&wqkvl, g_wqkvl);
    cudaGetSymbolAddress((void**)&wswh, g_wswh);   cudaGetSymbolAddress((void**)&wswl, g_wswl);
    cudaGetSymbolAddress((void**)&wqh2, g_wqh);    cudaGetSymbolAddress((void**)&wql2, g_wql);
    cudaGetSymbolAddress((void**)&wph, g_wph);     cudaGetSymbolAddress((void**)&wpl, g_wpl);
    float *bsw, *bwq, *bwp;
    cudaGetSymbolAddress((void**)&bsw, g_bsw);
    cudaGetSymbolAddress((void**)&bwq, g_bwq);
    cudaGetSymbolAddress((void**)&bwp, g_bwp);

    float* qkv  = arena;                 // 1,277,952 (1664*768)
    float* qsa  = arena + 1277952;       // 425,984
    float* q12  = arena + 1703936;       // 819,200
    float* wr   = arena + 2523136;       // 160,000
    float* wc   = arena + 2683136;       // 160,000
    float* pm   = arena + 2843136;       // 140,800
    float* ps   = arena + 2983936;       // 140,800
    float* pacc = arena + 3124736;       // 4,505,600

    FeatPtrs fp;
    for (int i = 0; i < 8; i++) fp.p[i] = (const float*)d_in[i];
    const float* qe   = (const float*)d_in[8];
    const float* ng   = (const float*)d_in[9];
    const float* nb   = (const float*)d_in[10];
    const float* wq   = (const float*)d_in[11];
    const float* wk   = (const float*)d_in[12];
    const float* wv   = (const float*)d_in[13];
    const float* wp   = (const float*)d_in[14];
    const float* bp   = (const float*)d_in[15];
    const float* wqkv = (const float*)d_in[16];
    const float* swp  = (const float*)d_in[17];
    const float* sbp  = (const float*)d_in[18];

    cudaFuncSetAttribute(k_kvgemm, cudaFuncAttributeMaxDynamicSharedMemorySize, 131072);
    cudaFuncSetAttribute(k_qgemm,  cudaFuncAttributeMaxDynamicSharedMemorySize, 131072);
    cudaFuncSetAttribute(k_cross,  cudaFuncAttributeMaxDynamicSharedMemorySize, 49152);

    k_init_q<<<1600, 256>>>(qe, qh, ql);
    k_tok_ln<<<dim3(680, 2), 256>>>(fp, ahi, alo);
    k_prep_w<<<12, 256>>>(wk, wv, ng, nb, whi, wlo, bkv);
    k_kvgemm<<<dim3(12, 2, 340), 512, 131072>>>(ahi, alo, whi, wlo, bkv, kvh, kvl);
    k_prep_wt<<<dim3(3, 6), 256>>>(wqkv, nullptr, nullptr, nullptr, wqkvh, wqkvl, nullptr, 768, 1.f);
    k_prep_wt<<<dim3(1, 6), 256>>>(swp, nullptr, nullptr, sbp, wswh, wswl, bsw, 256, 1.f);
    k_prep_wt<<<dim3(1, 6), 256>>>(wq, ng, nb, nullptr, wqh2, wql2, bwq, 256, 0.17677669529663687f);
    k_prep_wt<<<dim3(1, 6), 256>>>(wp, nullptr, nullptr, bp, wph, wpl, bwp, 256, 1.f);

    for (int d = 0; d < 6; d++){
        k_qgemm<<<dim3(13, 6), 256, 131072>>>(qh, ql,
            wqkvh + (size_t)d*768*256, wqkvl + (size_t)d*768*256,
            nullptr, qkv, 768, nullptr, nullptr);
        k_sa<<<dim3(8, 4, 4), 128>>>(qkv, oh, ol);
        k_qgemm<<<dim3(13, 2), 256, 131072>>>(oh, ol,
            wswh + (size_t)d*65536, wswl + (size_t)d*65536,
            bsw + d*256, qsa, 256, nullptr, nullptr);
        k_lnsplit<<<1600, 256>>>(qsa, xh, xl);
        k_qgemm<<<dim3(13, 2), 256, 131072>>>(xh, xl,
            wqh2 + (size_t)d*65536, wql2 + (size_t)d*65536,
            bwq + d*256, nullptr, 256, qnh, qnl);
        k_cross<<<dim3(22, 8, 8), 128, 49152>>>(qnh, qnl,
            kvh + (size_t)(2*d)*KVSZ,   kvl + (size_t)(2*d)*KVSZ,
            kvh + (size_t)(2*d+1)*KVSZ, kvl + (size_t)(2*d+1)*KVSZ,
            pm, ps, pacc);
        k_combine<<<dim3(4, 8, 8), 128>>>(pm, ps, pacc, och, ocl);
        k_qgemm<<<dim3(25, 2), 256, 131072>>>(och, ocl,
            wph + (size_t)d*65536, wpl + (size_t)d*65536,
            bwp + d*256, q12, 256, nullptr, nullptr);
        k_matchsm<<<16, 256, 10100*sizeof(float)>>>(q12, wr, wc);
        k_fuse<<<dim3(25, 16), 256>>>(qsa, q12, wr, wc, qh, ql,
                                      (d == 5) ? (float*)d_out : nullptr);
    }
}